// round 6
// baseline (speedup 1.0000x reference)
#include <cuda_runtime.h>
#include <cstdint>
#include <cstddef>

#define E_MAX   200000
#define D_IN    256
#define H_DIM   512
#define DO_DIM  256
#define B_GR    64

#define BM  128
#define BN  128
#define BK  32
#define PAD 4

// Scratch (allocation-free): intermediate h [E, H], precomputed ug [B, H],
// and normalized int32 batch indices.
__device__ float g_h[(size_t)E_MAX * H_DIM];
__device__ float g_ug[B_GR * H_DIM];
__device__ int   g_bidx[E_MAX];

__device__ __forceinline__ float to_tf32(float x) {
    uint32_t u;
    asm("cvt.rna.tf32.f32 %0, %1;" : "=r"(u) : "f"(x));
    return __uint_as_float(u);
}

__device__ __forceinline__ void mma_tf32(float* c, const uint32_t* a, const uint32_t* b) {
    asm volatile(
        "mma.sync.aligned.m16n8k8.row.col.f32.tf32.tf32.f32 "
        "{%0,%1,%2,%3}, {%4,%5,%6,%7}, {%8,%9}, {%0,%1,%2,%3};\n"
        : "+f"(c[0]), "+f"(c[1]), "+f"(c[2]), "+f"(c[3])
        : "r"(a[0]), "r"(a[1]), "r"(a[2]), "r"(a[3]), "r"(b[0]), "r"(b[1]));
}

// ---------------------------------------------------------------------------
// Normalize batch indices (int32 OR int64 source) into g_bidx[e] (int32).
// Detection per-block: int64 layout iff the first 128 candidate pairs all have
// a zero high word and a low word in [0, 64).
// ---------------------------------------------------------------------------
__global__ void bidx_kernel(const int* __restrict__ batch32, int E) {
    const int tid = threadIdx.x;

    __shared__ int s_is64;
    // threads 0..127 each vote on one candidate int64 pair
    bool ok = true;
    if (tid < 128) {
        int lo = batch32[2 * tid];
        int hi = batch32[2 * tid + 1];
        ok = (hi == 0) && (lo >= 0) && (lo < B_GR);
    }
    unsigned m = __ballot_sync(0xFFFFFFFFu, ok);
    __shared__ unsigned s_votes[8];
    if ((tid & 31) == 0) s_votes[tid >> 5] = m;
    __syncthreads();
    if (tid == 0) {
        bool all = true;
        for (int w = 0; w < 4; w++) all = all && (s_votes[w] == 0xFFFFFFFFu);
        s_is64 = all ? 1 : 0;
    }
    __syncthreads();
    const int is64 = s_is64;

    for (int e = blockIdx.x * blockDim.x + tid; e < E; e += gridDim.x * blockDim.x) {
        int v = is64 ? batch32[2 * e] : batch32[e];
        g_bidx[e] = v & (B_GR - 1);   // clamp: never out of range
    }
}

// ---------------------------------------------------------------------------
// Precompute ug[b][n] = b1[n] + sum_k u[b][k] * W1[768 + k][n]
// ---------------------------------------------------------------------------
__global__ void ug_kernel(const float* __restrict__ u, const float* __restrict__ W1,
                          const float* __restrict__ b1) {
    int b = blockIdx.x;
    __shared__ float us[D_IN];
    for (int i = threadIdx.x; i < D_IN; i += blockDim.x) us[i] = u[b * D_IN + i];
    __syncthreads();
    for (int n = threadIdx.x; n < H_DIM; n += blockDim.x) {
        float acc = b1[n];
        #pragma unroll 8
        for (int k = 0; k < D_IN; k++)
            acc += us[k] * W1[(size_t)(3 * D_IN + k) * H_DIM + n];
        g_ug[b * H_DIM + n] = acc;
    }
}

// ---------------------------------------------------------------------------
// GEMM1: h[e][n] = relu( src@W1a + dest@W1b + edge@W1c + ug[bidx[e]] )[n]
// Block tile 128x128, K = 768 in BK=32 chunks (each chunk maps to one source).
// ---------------------------------------------------------------------------
__global__ void __launch_bounds__(256)
gemm1_kernel(const float* __restrict__ src, const float* __restrict__ dest,
             const float* __restrict__ edge, const float* __restrict__ W1,
             int E) {
    __shared__ float As[BM][BK + PAD];
    __shared__ float Bs[BK][BN + PAD];

    const int e0 = blockIdx.y * BM;
    const int n0 = blockIdx.x * BN;   // n-blocks adjacent in bid -> L2 reuse of A

    const int tid  = threadIdx.x;
    const int lane = tid & 31;
    const int warp = tid >> 5;
    const int wRow = (warp >> 1) * 32;
    const int wCol = (warp & 1) * 64;

    float c[2][8][4];
    #pragma unroll
    for (int mt = 0; mt < 2; mt++)
        #pragma unroll
        for (int nt = 0; nt < 8; nt++)
            #pragma unroll
            for (int i = 0; i < 4; i++) c[mt][nt][i] = 0.f;

    const int arow = tid >> 3;          // 0..31
    const int acol = (tid & 7) * 4;     // 0..28
    const int brow = tid >> 5;          // 0..7
    const int bcol = lane * 4;          // 0..124

    for (int kt = 0; kt < 768 / BK; kt++) {
        const int kg = kt * BK;
        const float* Ap = (kg < 256) ? src : (kg < 512) ? dest : edge;
        const int kin = kg & 255;

        // Stage A tile (128 x 32), tf32-rounded
        #pragma unroll
        for (int p = 0; p < 4; p++) {
            int r = p * 32 + arow;
            int e = e0 + r;
            float4 v = make_float4(0.f, 0.f, 0.f, 0.f);
            if (e < E) v = *(const float4*)&Ap[(size_t)e * D_IN + kin + acol];
            As[r][acol + 0] = to_tf32(v.x);
            As[r][acol + 1] = to_tf32(v.y);
            As[r][acol + 2] = to_tf32(v.z);
            As[r][acol + 3] = to_tf32(v.w);
        }
        // Stage B tile (32 x 128), tf32-rounded
        #pragma unroll
        for (int p = 0; p < 4; p++) {
            int k = p * 8 + brow;
            float4 v = *(const float4*)&W1[(size_t)(kg + k) * H_DIM + n0 + bcol];
            Bs[k][bcol + 0] = to_tf32(v.x);
            Bs[k][bcol + 1] = to_tf32(v.y);
            Bs[k][bcol + 2] = to_tf32(v.z);
            Bs[k][bcol + 3] = to_tf32(v.w);
        }
        __syncthreads();

        #pragma unroll
        for (int kk = 0; kk < BK; kk += 8) {
            uint32_t a[2][4];
            uint32_t bf[8][2];
            const int kc = kk + (lane & 3);
            #pragma unroll
            for (int mt = 0; mt < 2; mt++) {
                int r = wRow + mt * 16 + (lane >> 2);
                a[mt][0] = __float_as_uint(As[r][kc]);
                a[mt][1] = __float_as_uint(As[r + 8][kc]);
                a[mt][2] = __float_as_uint(As[r][kc + 4]);
                a[mt][3] = __float_as_uint(As[r + 8][kc + 4]);
            }
            #pragma unroll
            for (int nt = 0; nt < 8; nt++) {
                int cc = wCol + nt * 8 + (lane >> 2);
                bf[nt][0] = __float_as_uint(Bs[kc][cc]);
                bf[nt][1] = __float_as_uint(Bs[kc + 4][cc]);
            }
            #pragma unroll
            for (int mt = 0; mt < 2; mt++)
                #pragma unroll
                for (int nt = 0; nt < 8; nt++)
                    mma_tf32(c[mt][nt], a[mt], bf[nt]);
        }
        __syncthreads();
    }

    // Epilogue: + ug[bidx[e]], ReLU, store to g_h
    #pragma unroll
    for (int mt = 0; mt < 2; mt++) {
        #pragma unroll
        for (int half = 0; half < 2; half++) {
            int r = wRow + mt * 16 + (lane >> 2) + half * 8;
            int e = e0 + r;
            if (e >= E) continue;
            int bg = g_bidx[e];
            const float* ugr = &g_ug[(size_t)bg * H_DIM + n0];
            float*       hr  = &g_h[(size_t)e * H_DIM + n0];
            #pragma unroll
            for (int nt = 0; nt < 8; nt++) {
                int col = wCol + nt * 8 + (lane & 3) * 2;
                float2 g = *(const float2*)&ugr[col];
                float2 o;
                o.x = fmaxf(c[mt][nt][half * 2 + 0] + g.x, 0.f);
                o.y = fmaxf(c[mt][nt][half * 2 + 1] + g.y, 0.f);
                *(float2*)&hr[col] = o;
            }
        }
    }
}

// ---------------------------------------------------------------------------
// GEMM2: out[e][n] = h[e] @ W2 + b2,  K = 512, N = 256
// ---------------------------------------------------------------------------
__global__ void __launch_bounds__(256)
gemm2_kernel(const float* __restrict__ W2, const float* __restrict__ b2,
             float* __restrict__ out, int E) {
    __shared__ float As[BM][BK + PAD];
    __shared__ float Bs[BK][BN + PAD];

    const int e0 = blockIdx.y * BM;
    const int n0 = blockIdx.x * BN;

    const int tid  = threadIdx.x;
    const int lane = tid & 31;
    const int warp = tid >> 5;
    const int wRow = (warp >> 1) * 32;
    const int wCol = (warp & 1) * 64;

    float c[2][8][4];
    #pragma unroll
    for (int mt = 0; mt < 2; mt++)
        #pragma unroll
        for (int nt = 0; nt < 8; nt++)
            #pragma unroll
            for (int i = 0; i < 4; i++) c[mt][nt][i] = 0.f;

    const int arow = tid >> 3;
    const int acol = (tid & 7) * 4;
    const int brow = tid >> 5;
    const int bcol = lane * 4;

    for (int kt = 0; kt < H_DIM / BK; kt++) {
        const int kg = kt * BK;

        #pragma unroll
        for (int p = 0; p < 4; p++) {
            int r = p * 32 + arow;
            int e = e0 + r;
            float4 v = make_float4(0.f, 0.f, 0.f, 0.f);
            if (e < E) v = *(const float4*)&g_h[(size_t)e * H_DIM + kg + acol];
            As[r][acol + 0] = to_tf32(v.x);
            As[r][acol + 1] = to_tf32(v.y);
            As[r][acol + 2] = to_tf32(v.z);
            As[r][acol + 3] = to_tf32(v.w);
        }
        #pragma unroll
        for (int p = 0; p < 4; p++) {
            int k = p * 8 + brow;
            float4 v = *(const float4*)&W2[(size_t)(kg + k) * DO_DIM + n0 + bcol];
            Bs[k][bcol + 0] = to_tf32(v.x);
            Bs[k][bcol + 1] = to_tf32(v.y);
            Bs[k][bcol + 2] = to_tf32(v.z);
            Bs[k][bcol + 3] = to_tf32(v.w);
        }
        __syncthreads();

        #pragma unroll
        for (int kk = 0; kk < BK; kk += 8) {
            uint32_t a[2][4];
            uint32_t bf[8][2];
            const int kc = kk + (lane & 3);
            #pragma unroll
            for (int mt = 0; mt < 2; mt++) {
                int r = wRow + mt * 16 + (lane >> 2);
                a[mt][0] = __float_as_uint(As[r][kc]);
                a[mt][1] = __float_as_uint(As[r + 8][kc]);
                a[mt][2] = __float_as_uint(As[r][kc + 4]);
                a[mt][3] = __float_as_uint(As[r + 8][kc + 4]);
            }
            #pragma unroll
            for (int nt = 0; nt < 8; nt++) {
                int cc = wCol + nt * 8 + (lane >> 2);
                bf[nt][0] = __float_as_uint(Bs[kc][cc]);
                bf[nt][1] = __float_as_uint(Bs[kc + 4][cc]);
            }
            #pragma unroll
            for (int mt = 0; mt < 2; mt++)
                #pragma unroll
                for (int nt = 0; nt < 8; nt++)
                    mma_tf32(c[mt][nt], a[mt], bf[nt]);
        }
        __syncthreads();
    }

    // Epilogue: + b2, store out
    #pragma unroll
    for (int mt = 0; mt < 2; mt++) {
        #pragma unroll
        for (int half = 0; half < 2; half++) {
            int r = wRow + mt * 16 + (lane >> 2) + half * 8;
            int e = e0 + r;
            if (e >= E) continue;
            float* orow = &out[(size_t)e * DO_DIM + n0];
            #pragma unroll
            for (int nt = 0; nt < 8; nt++) {
                int col = wCol + nt * 8 + (lane & 3) * 2;
                float2 bb = *(const float2*)&b2[n0 + col];
                float2 o;
                o.x = c[mt][nt][half * 2 + 0] + bb.x;
                o.y = c[mt][nt][half * 2 + 1] + bb.y;
                *(float2*)&orow[col] = o;
            }
        }
    }
}

// ---------------------------------------------------------------------------
// Inputs (metadata order): src, dest, edge_attr, u, batch, W1, b1, W2, b2
// ---------------------------------------------------------------------------
extern "C" void kernel_launch(void* const* d_in, const int* in_sizes, int n_in,
                              void* d_out, int out_size) {
    const float* src   = (const float*)d_in[0];
    const float* dest  = (const float*)d_in[1];
    const float* edge  = (const float*)d_in[2];
    const float* u     = (const float*)d_in[3];
    const int*   batch = (const int*)d_in[4];   // int32 view; bidx_kernel detects layout
    const float* W1    = (const float*)d_in[5];
    const float* b1    = (const float*)d_in[6];
    const float* W2    = (const float*)d_in[7];
    const float* b2    = (const float*)d_in[8];
    float* out = (float*)d_out;

    const int E  = in_sizes[4];          // element count == num edges
    const int EB = (E + BM - 1) / BM;

    bidx_kernel<<<256, 256>>>(batch, E);
    ug_kernel<<<B_GR, 256>>>(u, W1, b1);

    dim3 g1(H_DIM / BN, EB);             // x = n-block (adjacent bids share A rows)
    gemm1_kernel<<<g1, 256>>>(src, dest, edge, W1, E);

    dim3 g2(DO_DIM / BN, EB);
    gemm2_kernel<<<g2, 256>>>(W2, b2, out, E);
}

// round 7
// speedup vs baseline: 1.2761x; 1.2761x over previous
#include <cuda_runtime.h>
#include <cstdint>
#include <cstddef>

#define E_MAX   200064            // 200000 rounded up to BM multiple
#define D_IN    256
#define H_DIM   512
#define DO_DIM  256
#define B_GR    64

#define BM  128
#define BN  128
#define BK  32

#define ASTRIDE 36                // floats per A row  (bank = 4r+k, conflict-free)
#define BSTRIDE 136               // floats per B row  (bank = 8k+c, conflict-free)
#define A_FLOATS (BM * ASTRIDE)   // 4608
#define B_FLOATS (BK * BSTRIDE)   // 4352
#define STAGE_FLOATS (A_FLOATS + B_FLOATS)   // 8960
#define SMEM_BYTES (2 * STAGE_FLOATS * 4)    // 71680

// Allocation-free scratch
__device__ float g_h[(size_t)E_MAX * H_DIM];     // tf32-rounded activations
__device__ float g_ug[B_GR * H_DIM];
__device__ int   g_bidx[E_MAX];
__device__ float g_w1r[(size_t)3 * D_IN * H_DIM];  // W1[0:768] tf32-rounded
__device__ float g_w2r[(size_t)H_DIM * DO_DIM];    // W2 tf32-rounded

__device__ __forceinline__ float to_tf32(float x) {
    uint32_t u;
    asm("cvt.rna.tf32.f32 %0, %1;" : "=r"(u) : "f"(x));
    return __uint_as_float(u);
}

__device__ __forceinline__ void mma_tf32(float* c, const uint32_t* a, const uint32_t* b) {
    asm volatile(
        "mma.sync.aligned.m16n8k8.row.col.f32.tf32.tf32.f32 "
        "{%0,%1,%2,%3}, {%4,%5,%6,%7}, {%8,%9}, {%0,%1,%2,%3};\n"
        : "+f"(c[0]), "+f"(c[1]), "+f"(c[2]), "+f"(c[3])
        : "r"(a[0]), "r"(a[1]), "r"(a[2]), "r"(a[3]), "r"(b[0]), "r"(b[1]));
}

__device__ __forceinline__ void cp16(uint32_t saddr, const void* gaddr, uint32_t sz) {
    asm volatile("cp.async.cg.shared.global [%0], [%1], 16, %2;\n"
                 :: "r"(saddr), "l"(gaddr), "r"(sz));
}
__device__ __forceinline__ void cp_commit() { asm volatile("cp.async.commit_group;\n"); }
template <int N>
__device__ __forceinline__ void cp_wait() { asm volatile("cp.async.wait_group %0;\n" :: "n"(N)); }

// ---------------------------------------------------------------------------
// batch normalization (int32 or int64 source) -> g_bidx
// ---------------------------------------------------------------------------
__global__ void bidx_kernel(const int* __restrict__ batch32, int E) {
    const int tid = threadIdx.x;
    __shared__ int s_is64;
    bool ok = true;
    if (tid < 128) {
        int lo = batch32[2 * tid];
        int hi = batch32[2 * tid + 1];
        ok = (hi == 0) && (lo >= 0) && (lo < B_GR);
    }
    unsigned m = __ballot_sync(0xFFFFFFFFu, ok);
    __shared__ unsigned s_votes[8];
    if ((tid & 31) == 0) s_votes[tid >> 5] = m;
    __syncthreads();
    if (tid == 0) {
        bool all = true;
        for (int w = 0; w < 4; w++) all = all && (s_votes[w] == 0xFFFFFFFFu);
        s_is64 = all ? 1 : 0;
    }
    __syncthreads();
    const int is64 = s_is64;
    for (int e = blockIdx.x * blockDim.x + tid; e < E; e += gridDim.x * blockDim.x) {
        int v = is64 ? batch32[2 * e] : batch32[e];
        g_bidx[e] = v & (B_GR - 1);
    }
}

// ---------------------------------------------------------------------------
// Pre-round weights to tf32 (once; ~2MB traffic)
// ---------------------------------------------------------------------------
__global__ void prep_w(const float* __restrict__ W1, const float* __restrict__ W2) {
    const size_t n1 = (size_t)3 * D_IN * H_DIM;
    const size_t n2 = (size_t)H_DIM * DO_DIM;
    for (size_t i = (size_t)blockIdx.x * blockDim.x + threadIdx.x; i < n1 + n2;
         i += (size_t)gridDim.x * blockDim.x) {
        if (i < n1) g_w1r[i] = to_tf32(W1[i]);
        else        g_w2r[i - n1] = to_tf32(W2[i - n1]);
    }
}

// ---------------------------------------------------------------------------
// ug[b][n] = b1[n] + sum_k u[b][k] * W1[768+k][n]   (full fp32 precision)
// ---------------------------------------------------------------------------
__global__ void ug_kernel(const float* __restrict__ u, const float* __restrict__ W1,
                          const float* __restrict__ b1) {
    int b = blockIdx.x;
    __shared__ float us[D_IN];
    for (int i = threadIdx.x; i < D_IN; i += blockDim.x) us[i] = u[b * D_IN + i];
    __syncthreads();
    for (int n = threadIdx.x; n < H_DIM; n += blockDim.x) {
        float acc = b1[n];
        #pragma unroll 8
        for (int k = 0; k < D_IN; k++)
            acc += us[k] * W1[(size_t)(3 * D_IN + k) * H_DIM + n];
        g_ug[b * H_DIM + n] = acc;
    }
}

// ---------------------------------------------------------------------------
// GEMM1: h = relu(src@W1a + dest@W1b + edge@W1c + ug[bidx]) -> g_h (tf32)
// 2-stage cp.async pipeline, 128x128x32 tiles, K=768
// ---------------------------------------------------------------------------
__global__ void __launch_bounds__(256, 2)
gemm1_kernel(const float* __restrict__ src, const float* __restrict__ dest,
             const float* __restrict__ edge, int E) {
    extern __shared__ float smem[];
    const uint32_t sbase = (uint32_t)__cvta_generic_to_shared(smem);

    const int e0 = blockIdx.y * BM;
    const int n0 = blockIdx.x * BN;

    const int tid  = threadIdx.x;
    const int lane = tid & 31;
    const int warp = tid >> 5;
    const int wRow = (warp >> 1) * 32;
    const int wCol = (warp & 1) * 64;

    float c[2][8][4];
    #pragma unroll
    for (int mt = 0; mt < 2; mt++)
        #pragma unroll
        for (int nt = 0; nt < 8; nt++)
            #pragma unroll
            for (int i = 0; i < 4; i++) c[mt][nt][i] = 0.f;

    // cp.async chunk maps (each thread: 4 A chunks + 4 B chunks per tile)
    const int aRow = tid >> 1;                 // with i*128 stepping: rows 0..127, 8 chunks/row
    const int aChk = (tid & 1) * 4;            // chunk base within row (i adds 0..3)
    const int bRow = tid >> 3;                 // rows 0..31
    const int bChk = (tid & 7) * 4;

    auto stage = [&](int kt, int buf) {
        const int kg  = kt * BK;
        const float* Ap = (kg < 256) ? src : (kg < 512) ? dest : edge;
        const int kin = kg & 255;
        const uint32_t sa = sbase + (uint32_t)(buf * STAGE_FLOATS) * 4;
        const uint32_t sb = sa + A_FLOATS * 4;
        // A tile: 128 rows x 8 chunks
        #pragma unroll
        for (int i = 0; i < 4; i++) {
            int row = aRow;                    // 0..127
            int c4  = aChk + i;                // 0..7
            int e   = e0 + row;
            int ec  = (e < E) ? e : (E - 1);
            const float* g = Ap + (size_t)ec * D_IN + kin + c4 * 4;
            cp16(sa + (uint32_t)(row * ASTRIDE + c4 * 4) * 4, g, (e < E) ? 16u : 0u);
        }
        // B tile: 32 rows x 32 chunks (pre-rounded W1)
        #pragma unroll
        for (int i = 0; i < 4; i++) {
            int row = bRow;                    // 0..31
            int c4  = bChk + i;                // 0..31
            const float* g = g_w1r + (size_t)(kg + row) * H_DIM + n0 + c4 * 4;
            cp16(sb + (uint32_t)(row * BSTRIDE + c4 * 4) * 4, g, 16u);
        }
        cp_commit();
    };

    stage(0, 0);
    int buf = 0;
    const int KT = (3 * D_IN) / BK;            // 24

    for (int kt = 0; kt < KT; kt++) {
        if (kt + 1 < KT) { stage(kt + 1, buf ^ 1); cp_wait<1>(); }
        else             { cp_wait<0>(); }
        __syncthreads();

        const float* As = smem + buf * STAGE_FLOATS;
        const float* Bs = As + A_FLOATS;

        #pragma unroll
        for (int kk = 0; kk < BK; kk += 8) {
            uint32_t a[2][4];
            uint32_t bf[8][2];
            const int kc = kk + (lane & 3);
            #pragma unroll
            for (int mt = 0; mt < 2; mt++) {
                int r = wRow + mt * 16 + (lane >> 2);
                a[mt][0] = __float_as_uint(to_tf32(As[r * ASTRIDE + kc]));
                a[mt][1] = __float_as_uint(to_tf32(As[(r + 8) * ASTRIDE + kc]));
                a[mt][2] = __float_as_uint(to_tf32(As[r * ASTRIDE + kc + 4]));
                a[mt][3] = __float_as_uint(to_tf32(As[(r + 8) * ASTRIDE + kc + 4]));
            }
            #pragma unroll
            for (int nt = 0; nt < 8; nt++) {
                int cc = wCol + nt * 8 + (lane >> 2);
                bf[nt][0] = __float_as_uint(Bs[kc * BSTRIDE + cc]);
                bf[nt][1] = __float_as_uint(Bs[(kc + 4) * BSTRIDE + cc]);
            }
            #pragma unroll
            for (int mt = 0; mt < 2; mt++)
                #pragma unroll
                for (int nt = 0; nt < 8; nt++)
                    mma_tf32(c[mt][nt], a[mt], bf[nt]);
        }
        __syncthreads();
        buf ^= 1;
    }

    // Epilogue: + ug[bidx[e]], ReLU, tf32-round, store to g_h
    #pragma unroll
    for (int mt = 0; mt < 2; mt++) {
        #pragma unroll
        for (int half = 0; half < 2; half++) {
            int r = wRow + mt * 16 + (lane >> 2) + half * 8;
            int e = e0 + r;
            if (e >= E) continue;
            int bg = g_bidx[e];
            const float* ugr = &g_ug[(size_t)bg * H_DIM + n0];
            float*       hr  = &g_h[(size_t)e * H_DIM + n0];
            #pragma unroll
            for (int nt = 0; nt < 8; nt++) {
                int col = wCol + nt * 8 + (lane & 3) * 2;
                float2 g = *(const float2*)&ugr[col];
                float2 o;
                o.x = to_tf32(fmaxf(c[mt][nt][half * 2 + 0] + g.x, 0.f));
                o.y = to_tf32(fmaxf(c[mt][nt][half * 2 + 1] + g.y, 0.f));
                *(float2*)&hr[col] = o;
            }
        }
    }
}

// ---------------------------------------------------------------------------
// GEMM2: out = g_h @ W2r + b2   (all operands pre-rounded: no cvt in loop)
// ---------------------------------------------------------------------------
__global__ void __launch_bounds__(256, 2)
gemm2_kernel(const float* __restrict__ b2, float* __restrict__ out, int E) {
    extern __shared__ float smem[];
    const uint32_t sbase = (uint32_t)__cvta_generic_to_shared(smem);

    const int e0 = blockIdx.y * BM;
    const int n0 = blockIdx.x * BN;

    const int tid  = threadIdx.x;
    const int lane = tid & 31;
    const int warp = tid >> 5;
    const int wRow = (warp >> 1) * 32;
    const int wCol = (warp & 1) * 64;

    float c[2][8][4];
    #pragma unroll
    for (int mt = 0; mt < 2; mt++)
        #pragma unroll
        for (int nt = 0; nt < 8; nt++)
            #pragma unroll
            for (int i = 0; i < 4; i++) c[mt][nt][i] = 0.f;

    const int aRow = tid >> 1;
    const int aChk = (tid & 1) * 4;
    const int bRow = tid >> 3;
    const int bChk = (tid & 7) * 4;

    auto stage = [&](int kt, int buf) {
        const int kg = kt * BK;
        const uint32_t sa = sbase + (uint32_t)(buf * STAGE_FLOATS) * 4;
        const uint32_t sb = sa + A_FLOATS * 4;
        #pragma unroll
        for (int i = 0; i < 4; i++) {
            int row = aRow;
            int c4  = aChk + i;
            int e   = e0 + row;                 // g_h sized E_MAX (BM multiple): in bounds
            const float* g = g_h + (size_t)e * H_DIM + kg + c4 * 4;
            cp16(sa + (uint32_t)(row * ASTRIDE + c4 * 4) * 4, g, 16u);
        }
        #pragma unroll
        for (int i = 0; i < 4; i++) {
            int row = bRow;
            int c4  = bChk + i;
            const float* g = g_w2r + (size_t)(kg + row) * DO_DIM + n0 + c4 * 4;
            cp16(sb + (uint32_t)(row * BSTRIDE + c4 * 4) * 4, g, 16u);
        }
        cp_commit();
    };

    stage(0, 0);
    int buf = 0;
    const int KT = H_DIM / BK;                  // 16

    for (int kt = 0; kt < KT; kt++) {
        if (kt + 1 < KT) { stage(kt + 1, buf ^ 1); cp_wait<1>(); }
        else             { cp_wait<0>(); }
        __syncthreads();

        const float* As = smem + buf * STAGE_FLOATS;
        const float* Bs = As + A_FLOATS;

        #pragma unroll
        for (int kk = 0; kk < BK; kk += 8) {
            uint32_t a[2][4];
            uint32_t bf[8][2];
            const int kc = kk + (lane & 3);
            #pragma unroll
            for (int mt = 0; mt < 2; mt++) {
                int r = wRow + mt * 16 + (lane >> 2);
                a[mt][0] = __float_as_uint(As[r * ASTRIDE + kc]);
                a[mt][1] = __float_as_uint(As[(r + 8) * ASTRIDE + kc]);
                a[mt][2] = __float_as_uint(As[r * ASTRIDE + kc + 4]);
                a[mt][3] = __float_as_uint(As[(r + 8) * ASTRIDE + kc + 4]);
            }
            #pragma unroll
            for (int nt = 0; nt < 8; nt++) {
                int cc = wCol + nt * 8 + (lane >> 2);
                bf[nt][0] = __float_as_uint(Bs[kc * BSTRIDE + cc]);
                bf[nt][1] = __float_as_uint(Bs[(kc + 4) * BSTRIDE + cc]);
            }
            #pragma unroll
            for (int mt = 0; mt < 2; mt++)
                #pragma unroll
                for (int nt = 0; nt < 8; nt++)
                    mma_tf32(c[mt][nt], a[mt], bf[nt]);
        }
        __syncthreads();
        buf ^= 1;
    }

    // Epilogue: + b2, store out
    #pragma unroll
    for (int mt = 0; mt < 2; mt++) {
        #pragma unroll
        for (int half = 0; half < 2; half++) {
            int r = wRow + mt * 16 + (lane >> 2) + half * 8;
            int e = e0 + r;
            if (e >= E) continue;
            float* orow = &out[(size_t)e * DO_DIM + n0];
            #pragma unroll
            for (int nt = 0; nt < 8; nt++) {
                int col = wCol + nt * 8 + (lane & 3) * 2;
                float2 bb = *(const float2*)&b2[n0 + col];
                float2 o;
                o.x = c[mt][nt][half * 2 + 0] + bb.x;
                o.y = c[mt][nt][half * 2 + 1] + bb.y;
                *(float2*)&orow[col] = o;
            }
        }
    }
}

// ---------------------------------------------------------------------------
// Inputs (metadata order): src, dest, edge_attr, u, batch, W1, b1, W2, b2
// ---------------------------------------------------------------------------
extern "C" void kernel_launch(void* const* d_in, const int* in_sizes, int n_in,
                              void* d_out, int out_size) {
    const float* src   = (const float*)d_in[0];
    const float* dest  = (const float*)d_in[1];
    const float* edge  = (const float*)d_in[2];
    const float* u     = (const float*)d_in[3];
    const int*   batch = (const int*)d_in[4];
    const float* W1    = (const float*)d_in[5];
    const float* b1    = (const float*)d_in[6];
    const float* W2    = (const float*)d_in[7];
    const float* b2    = (const float*)d_in[8];
    float* out = (float*)d_out;

    const int E  = in_sizes[4];
    const int EB = (E + BM - 1) / BM;

    static bool attr_set = false;
    if (!attr_set) {
        cudaFuncSetAttribute(gemm1_kernel, cudaFuncAttributeMaxDynamicSharedMemorySize, SMEM_BYTES);
        cudaFuncSetAttribute(gemm2_kernel, cudaFuncAttributeMaxDynamicSharedMemorySize, SMEM_BYTES);
        attr_set = true;
    }

    bidx_kernel<<<256, 256>>>(batch, E);
    prep_w<<<256, 256>>>(W1, W2);
    ug_kernel<<<B_GR, 256>>>(u, W1, b1);

    dim3 g1(H_DIM / BN, EB);
    gemm1_kernel<<<g1, 256, SMEM_BYTES>>>(src, dest, edge, E);

    dim3 g2(DO_DIM / BN, EB);
    gemm2_kernel<<<g2, 256, SMEM_BYTES>>>(b2, out, E);
}

// round 9
// speedup vs baseline: 1.2883x; 1.0096x over previous
#include <cuda_runtime.h>
#include <cstdint>
#include <cstddef>

#define D_IN    256
#define H_DIM   512
#define DO_DIM  256
#define B_GR    64

#define BM  128
#define BN  128
#define BK  32
#define E_MAX 200064                 // multiple of BM

#define TSTRIDE 36                   // floats per tile row (144B = 9*16B -> LDSM conflict-free)
#define TILE_FLOATS (128 * TSTRIDE)  // 4608 floats per (128 x 32) tile
#define STAGE_FLOATS (2 * TILE_FLOATS)
#define SMEM_BYTES (2 * STAGE_FLOATS * 4)   // 73728

// Allocation-free scratch
__device__ float g_h[(size_t)E_MAX * H_DIM];         // tf32-rounded activations
__device__ float g_ug[B_GR * H_DIM];
__device__ int   g_bidx[E_MAX];
__device__ float g_w1t[(size_t)H_DIM * (3 * D_IN)];  // W1^T [n=512][k=768], tf32-rounded
__device__ float g_w2t[(size_t)DO_DIM * H_DIM];      // W2^T [n=256][k=512], tf32-rounded

__device__ __forceinline__ float to_tf32(float x) {
    uint32_t u;
    asm("cvt.rna.tf32.f32 %0, %1;" : "=r"(u) : "f"(x));
    return __uint_as_float(u);
}
__device__ __forceinline__ uint32_t tf32r(float x) {
    uint32_t u;
    asm("cvt.rna.tf32.f32 %0, %1;" : "=r"(u) : "f"(x));
    return u;
}
__device__ __forceinline__ void mma_tf32(float* c, const uint32_t* a, const uint32_t* b) {
    asm volatile(
        "mma.sync.aligned.m16n8k8.row.col.f32.tf32.tf32.f32 "
        "{%0,%1,%2,%3}, {%4,%5,%6,%7}, {%8,%9}, {%0,%1,%2,%3};\n"
        : "+f"(c[0]), "+f"(c[1]), "+f"(c[2]), "+f"(c[3])
        : "r"(a[0]), "r"(a[1]), "r"(a[2]), "r"(a[3]), "r"(b[0]), "r"(b[1]));
}
__device__ __forceinline__ void ldsm4(uint32_t* r, uint32_t saddr) {
    asm volatile("ldmatrix.sync.aligned.m8n8.x4.shared.b16 {%0,%1,%2,%3}, [%4];"
                 : "=r"(r[0]), "=r"(r[1]), "=r"(r[2]), "=r"(r[3]) : "r"(saddr));
}
__device__ __forceinline__ void cp16(uint32_t saddr, const void* gaddr, uint32_t sz) {
    asm volatile("cp.async.cg.shared.global [%0], [%1], 16, %2;\n"
                 :: "r"(saddr), "l"(gaddr), "r"(sz));
}
__device__ __forceinline__ void cp_commit() { asm volatile("cp.async.commit_group;\n"); }
template <int N>
__device__ __forceinline__ void cp_wait() { asm volatile("cp.async.wait_group %0;\n" :: "n"(N)); }

// ---------------------------------------------------------------------------
// batch index normalization (int32 or int64 source) -> g_bidx
// ---------------------------------------------------------------------------
__global__ void bidx_kernel(const int* __restrict__ batch32, int E) {
    const int tid = threadIdx.x;
    __shared__ int s_is64;
    bool ok = true;
    if (tid < 128) {
        int lo = batch32[2 * tid];
        int hi = batch32[2 * tid + 1];
        ok = (hi == 0) && (lo >= 0) && (lo < B_GR);
    }
    unsigned m = __ballot_sync(0xFFFFFFFFu, ok);
    __shared__ unsigned s_votes[8];
    if ((tid & 31) == 0) s_votes[tid >> 5] = m;
    __syncthreads();
    if (tid == 0) {
        bool all = true;
        for (int w = 0; w < 4; w++) all = all && (s_votes[w] == 0xFFFFFFFFu);
        s_is64 = all ? 1 : 0;
    }
    __syncthreads();
    const int is64 = s_is64;
    for (int e = blockIdx.x * blockDim.x + tid; e < E; e += gridDim.x * blockDim.x) {
        int v = is64 ? batch32[2 * e] : batch32[e];
        g_bidx[e] = v & (B_GR - 1);
    }
}

// ---------------------------------------------------------------------------
// Weight prep: transpose to [n][k] + tf32 round (once; ~2MB)
// ---------------------------------------------------------------------------
__global__ void prep_w(const float* __restrict__ W1, const float* __restrict__ W2) {
    const size_t n1 = (size_t)H_DIM * (3 * D_IN);
    const size_t n2 = (size_t)DO_DIM * H_DIM;
    for (size_t i = (size_t)blockIdx.x * blockDim.x + threadIdx.x; i < n1 + n2;
         i += (size_t)gridDim.x * blockDim.x) {
        if (i < n1) {
            int n = (int)(i / (3 * D_IN));
            int k = (int)(i % (3 * D_IN));
            g_w1t[i] = to_tf32(W1[(size_t)k * H_DIM + n]);
        } else {
            size_t o = i - n1;
            int n = (int)(o / H_DIM);
            int k = (int)(o % H_DIM);
            g_w2t[o] = to_tf32(W2[(size_t)k * DO_DIM + n]);
        }
    }
}

// ---------------------------------------------------------------------------
// ug[b][n] = b1[n] + sum_k u[b][k] * W1[768+k][n]  (fp32)
// ---------------------------------------------------------------------------
__global__ void ug_kernel(const float* __restrict__ u, const float* __restrict__ W1,
                          const float* __restrict__ b1) {
    int b = blockIdx.x;
    __shared__ float us[D_IN];
    for (int i = threadIdx.x; i < D_IN; i += blockDim.x) us[i] = u[b * D_IN + i];
    __syncthreads();
    for (int n = threadIdx.x; n < H_DIM; n += blockDim.x) {
        float acc = b1[n];
        #pragma unroll 8
        for (int k = 0; k < D_IN; k++)
            acc += us[k] * W1[(size_t)(3 * D_IN + k) * H_DIM + n];
        g_ug[b * H_DIM + n] = acc;
    }
}

// ---------------------------------------------------------------------------
// GEMM with ldmatrix-fed m16n8k8 tf32.
// MODE 1: h = relu(cat(src,dest,edge)@W1abc + ug[bidx]) -> g_h (tf32-rounded)
// MODE 2: out = g_h @ W2 + b2
// CTA 128x128x32, 8 warps (warp tile 32x64), 2-stage cp.async pipeline.
// Smem tiles (A and B) both stored as 128 rows x 32 cols, stride 36 floats.
// A rows = edges (k-major);  B rows = n (k-major, weights pre-transposed).
// ---------------------------------------------------------------------------
template <int MODE>
__global__ void __launch_bounds__(256, 2)
mlp_gemm(const float* __restrict__ A0, const float* __restrict__ A1,
         const float* __restrict__ A2, const float* __restrict__ bias2,
         float* __restrict__ out, int E) {
    extern __shared__ float smem[];
    const uint32_t sbase = (uint32_t)__cvta_generic_to_shared(smem);

    const int e0 = blockIdx.y * BM;
    const int n0 = blockIdx.x * BN;

    const int tid  = threadIdx.x;
    const int lane = tid & 31;
    const int warp = tid >> 5;
    const int wRow = (warp >> 1) * 32;     // warp m-offset (4 m-groups)
    const int wCol = (warp & 1) * 64;      // warp n-offset (2 n-groups)

    float c[2][8][4];
    #pragma unroll
    for (int mt = 0; mt < 2; mt++)
        #pragma unroll
        for (int nt = 0; nt < 8; nt++)
            #pragma unroll
            for (int i = 0; i < 4; i++) c[mt][nt][i] = 0.f;

    // ldmatrix lane->address maps (byte offsets within a tile)
    // A, per mt: rows wRow+mt*16+(lane&15), col sel (lane>>4)*4
    uint32_t aOff[2];
    #pragma unroll
    for (int mt = 0; mt < 2; mt++) {
        int r  = wRow + mt * 16 + (lane & 15);
        int cs = (lane >> 4) * 4;
        aOff[mt] = (uint32_t)(r * TSTRIDE + cs) * 4;
    }
    // B, per nt-pair pp: rows wCol + pp*16 + ((lane>>4)?8:0) + (lane&7), col sel ((lane>>3)&1)*4
    uint32_t bOff[4];
    #pragma unroll
    for (int pp = 0; pp < 4; pp++) {
        int r  = wCol + pp * 16 + ((lane >> 4) ? 8 : 0) + (lane & 7);
        int cs = ((lane >> 3) & 1) * 4;
        bOff[pp] = (uint32_t)(r * TSTRIDE + cs) * 4;
    }

    // cp.async staging map: both tiles 128 rows x 8 chunks of 16B
    const int sRow = tid >> 1;             // 0..127
    const int sChk = (tid & 1) * 4;        // chunk base; +i gives 0..7

    constexpr int KT   = (MODE == 1) ? (3 * D_IN) / BK : H_DIM / BK;   // 24 / 16
    constexpr int KDIM = (MODE == 1) ? (3 * D_IN) : H_DIM;

    auto stage = [&](int kt, int buf) {
        const int kg = kt * BK;
        const uint32_t sA = sbase + (uint32_t)(buf * STAGE_FLOATS) * 4;
        const uint32_t sB = sA + TILE_FLOATS * 4;
        const float* Ap;
        int kin;
        if (MODE == 1) {
            Ap  = (kg < 256) ? A0 : (kg < 512) ? A1 : A2;
            kin = kg & 255;
        } else {
            Ap  = g_h;
            kin = kg;
        }
        const float* Bp = (MODE == 1) ? g_w1t : g_w2t;
        #pragma unroll
        for (int i = 0; i < 4; i++) {
            const int c4 = sChk + i;
            const uint32_t so = (uint32_t)(sRow * TSTRIDE + c4 * 4) * 4;
            if (MODE == 1) {
                const int e = e0 + sRow;
                const int ec = (e < E) ? e : 0;
                cp16(sA + so, Ap + (size_t)ec * D_IN + kin + c4 * 4, (e < E) ? 16u : 0u);
            } else {
                cp16(sA + so, Ap + (size_t)(e0 + sRow) * H_DIM + kin + c4 * 4, 16u);
            }
            cp16(sB + so, Bp + (size_t)(n0 + sRow) * KDIM + kg + c4 * 4, 16u);
        }
        cp_commit();
    };

    stage(0, 0);
    int buf = 0;

    for (int kt = 0; kt < KT; kt++) {
        if (kt + 1 < KT) { stage(kt + 1, buf ^ 1); cp_wait<1>(); }
        else             { cp_wait<0>(); }
        __syncthreads();

        const uint32_t sA = sbase + (uint32_t)(buf * STAGE_FLOATS) * 4;
        const uint32_t sB = sA + TILE_FLOATS * 4;

        #pragma unroll
        for (int kk = 0; kk < BK; kk += 8) {
            uint32_t a[2][4];
            uint32_t b[4][4];
            #pragma unroll
            for (int mt = 0; mt < 2; mt++) {
                ldsm4(a[mt], sA + aOff[mt] + kk * 4);
                if (MODE == 1) {
                    #pragma unroll
                    for (int j = 0; j < 4; j++)
                        a[mt][j] = tf32r(__uint_as_float(a[mt][j]));
                }
            }
            #pragma unroll
            for (int pp = 0; pp < 4; pp++)
                ldsm4(b[pp], sB + bOff[pp] + kk * 4);

            #pragma unroll
            for (int mt = 0; mt < 2; mt++)
                #pragma unroll
                for (int nt = 0; nt < 8; nt++)
                    mma_tf32(c[mt][nt], a[mt], &b[nt >> 1][(nt & 1) * 2]);
        }
        __syncthreads();
        buf ^= 1;
    }

    // Epilogue
    #pragma unroll
    for (int mt = 0; mt < 2; mt++) {
        #pragma unroll
        for (int half = 0; half < 2; half++) {
            int r = wRow + mt * 16 + (lane >> 2) + half * 8;
            int e = e0 + r;
            if (e >= E) continue;
            if (MODE == 1) {
                int bg = g_bidx[e];
                const float* ugr = &g_ug[(size_t)bg * H_DIM + n0];
                float*       hr  = &g_h[(size_t)e * H_DIM + n0];
                #pragma unroll
                for (int nt = 0; nt < 8; nt++) {
                    int col = wCol + nt * 8 + (lane & 3) * 2;
                    float2 g = *(const float2*)&ugr[col];
                    float2 o;
                    o.x = to_tf32(fmaxf(c[mt][nt][half * 2 + 0] + g.x, 0.f));
                    o.y = to_tf32(fmaxf(c[mt][nt][half * 2 + 1] + g.y, 0.f));
                    *(float2*)&hr[col] = o;
                }
            } else {
                float* orow = &out[(size_t)e * DO_DIM + n0];
                #pragma unroll
                for (int nt = 0; nt < 8; nt++) {
                    int col = wCol + nt * 8 + (lane & 3) * 2;
                    float2 bb = *(const float2*)&bias2[col + n0];
                    float2 o;
                    o.x = c[mt][nt][half * 2 + 0] + bb.x;
                    o.y = c[mt][nt][half * 2 + 1] + bb.y;
                    *(float2*)&orow[col] = o;
                }
            }
        }
    }
}

// ---------------------------------------------------------------------------
// Inputs (metadata order): src, dest, edge_attr, u, batch, W1, b1, W2, b2
// ---------------------------------------------------------------------------
extern "C" void kernel_launch(void* const* d_in, const int* in_sizes, int n_in,
                              void* d_out, int out_size) {
    const float* src   = (const float*)d_in[0];
    const float* dest  = (const float*)d_in[1];
    const float* edge  = (const float*)d_in[2];
    const float* u     = (const float*)d_in[3];
    const int*   batch = (const int*)d_in[4];
    const float* W1    = (const float*)d_in[5];
    const float* b1    = (const float*)d_in[6];
    const float* W2    = (const float*)d_in[7];
    const float* b2    = (const float*)d_in[8];
    float* out = (float*)d_out;

    const int E  = in_sizes[4];
    const int EB = (E + BM - 1) / BM;

    static bool attr_set = false;
    if (!attr_set) {
        cudaFuncSetAttribute(mlp_gemm<1>, cudaFuncAttributeMaxDynamicSharedMemorySize, SMEM_BYTES);
        cudaFuncSetAttribute(mlp_gemm<2>, cudaFuncAttributeMaxDynamicSharedMemorySize, SMEM_BYTES);
        attr_set = true;
    }

    bidx_kernel<<<256, 256>>>(batch, E);
    prep_w<<<256, 256>>>(W1, W2);
    ug_kernel<<<B_GR, 256>>>(u, W1, b1);

    dim3 g1(H_DIM / BN, EB);     // n-tiles adjacent -> A rows reused in L2
    mlp_gemm<1><<<g1, 256, SMEM_BYTES>>>(src, dest, edge, nullptr, nullptr, E);

    dim3 g2(DO_DIM / BN, EB);
    mlp_gemm<2><<<g2, 256, SMEM_BYTES>>>(nullptr, nullptr, nullptr, b2, out, E);
}

// round 10
// speedup vs baseline: 1.3400x; 1.0402x over previous
#include <cuda_runtime.h>
#include <cstdint>
#include <cstddef>

#define D_IN    256
#define H_DIM   512
#define DO_DIM  256
#define B_GR    64

#define BM  128
#define BN  128
#define BK  32
#define E_MAX 200064                 // multiple of BM

#define TSTRIDE 36                   // floats per tile row (144B = 9*16B -> LDSM conflict-free)
#define TILE_FLOATS (128 * TSTRIDE)  // 4608 floats per (128 x 32) tile
#define STAGE_FLOATS (2 * TILE_FLOATS)      // A + B
#define STAGES 3
#define SMEM_BYTES (STAGES * STAGE_FLOATS * 4)   // 110592

// Allocation-free scratch
__device__ float g_h[(size_t)E_MAX * H_DIM];         // tf32-rounded activations
__device__ float g_ug[B_GR * H_DIM];
__device__ int   g_bidx[E_MAX];
__device__ float g_w1t[(size_t)H_DIM * (3 * D_IN)];  // W1^T [n=512][k=768], tf32-rounded
__device__ float g_w2t[(size_t)DO_DIM * H_DIM];      // W2^T [n=256][k=512], tf32-rounded

__device__ __forceinline__ float to_tf32(float x) {
    uint32_t u;
    asm("cvt.rna.tf32.f32 %0, %1;" : "=r"(u) : "f"(x));
    return __uint_as_float(u);
}
__device__ __forceinline__ uint32_t tf32r(float x) {
    uint32_t u;
    asm("cvt.rna.tf32.f32 %0, %1;" : "=r"(u) : "f"(x));
    return u;
}
__device__ __forceinline__ void mma_tf32(float* c, const uint32_t* a, const uint32_t* b) {
    asm volatile(
        "mma.sync.aligned.m16n8k8.row.col.f32.tf32.tf32.f32 "
        "{%0,%1,%2,%3}, {%4,%5,%6,%7}, {%8,%9}, {%0,%1,%2,%3};\n"
        : "+f"(c[0]), "+f"(c[1]), "+f"(c[2]), "+f"(c[3])
        : "r"(a[0]), "r"(a[1]), "r"(a[2]), "r"(a[3]), "r"(b[0]), "r"(b[1]));
}
__device__ __forceinline__ void ldsm4(uint32_t* r, uint32_t saddr) {
    asm volatile("ldmatrix.sync.aligned.m8n8.x4.shared.b16 {%0,%1,%2,%3}, [%4];"
                 : "=r"(r[0]), "=r"(r[1]), "=r"(r[2]), "=r"(r[3]) : "r"(saddr));
}
__device__ __forceinline__ void cp16(uint32_t saddr, const void* gaddr, uint32_t sz) {
    asm volatile("cp.async.cg.shared.global [%0], [%1], 16, %2;\n"
                 :: "r"(saddr), "l"(gaddr), "r"(sz));
}
__device__ __forceinline__ void cp_commit() { asm volatile("cp.async.commit_group;\n"); }
template <int N>
__device__ __forceinline__ void cp_wait() { asm volatile("cp.async.wait_group %0;\n" :: "n"(N)); }

// ---------------------------------------------------------------------------
// batch index normalization (int32 or int64 source) -> g_bidx
// ---------------------------------------------------------------------------
__global__ void bidx_kernel(const int* __restrict__ batch32, int E) {
    const int tid = threadIdx.x;
    __shared__ int s_is64;
    bool ok = true;
    if (tid < 128) {
        int lo = batch32[2 * tid];
        int hi = batch32[2 * tid + 1];
        ok = (hi == 0) && (lo >= 0) && (lo < B_GR);
    }
    unsigned m = __ballot_sync(0xFFFFFFFFu, ok);
    __shared__ unsigned s_votes[8];
    if ((tid & 31) == 0) s_votes[tid >> 5] = m;
    __syncthreads();
    if (tid == 0) {
        bool all = true;
        for (int w = 0; w < 4; w++) all = all && (s_votes[w] == 0xFFFFFFFFu);
        s_is64 = all ? 1 : 0;
    }
    __syncthreads();
    const int is64 = s_is64;
    for (int e = blockIdx.x * blockDim.x + tid; e < E; e += gridDim.x * blockDim.x) {
        int v = is64 ? batch32[2 * e] : batch32[e];
        g_bidx[e] = v & (B_GR - 1);
    }
}

// ---------------------------------------------------------------------------
// Weight prep: transpose to [n][k] + tf32 round (once; ~2MB)
// ---------------------------------------------------------------------------
__global__ void prep_w(const float* __restrict__ W1, const float* __restrict__ W2) {
    const size_t n1 = (size_t)H_DIM * (3 * D_IN);
    const size_t n2 = (size_t)DO_DIM * H_DIM;
    for (size_t i = (size_t)blockIdx.x * blockDim.x + threadIdx.x; i < n1 + n2;
         i += (size_t)gridDim.x * blockDim.x) {
        if (i < n1) {
            int n = (int)(i / (3 * D_IN));
            int k = (int)(i % (3 * D_IN));
            g_w1t[i] = to_tf32(W1[(size_t)k * H_DIM + n]);
        } else {
            size_t o = i - n1;
            int n = (int)(o / H_DIM);
            int k = (int)(o % H_DIM);
            g_w2t[o] = to_tf32(W2[(size_t)k * DO_DIM + n]);
        }
    }
}

// ---------------------------------------------------------------------------
// ug[b][n] = b1[n] + sum_k u[b][k] * W1[768+k][n]  (fp32)
// ---------------------------------------------------------------------------
__global__ void ug_kernel(const float* __restrict__ u, const float* __restrict__ W1,
                          const float* __restrict__ b1) {
    int b = blockIdx.x;
    __shared__ float us[D_IN];
    for (int i = threadIdx.x; i < D_IN; i += blockDim.x) us[i] = u[b * D_IN + i];
    __syncthreads();
    for (int n = threadIdx.x; n < H_DIM; n += blockDim.x) {
        float acc = b1[n];
        #pragma unroll 8
        for (int k = 0; k < D_IN; k++)
            acc += us[k] * W1[(size_t)(3 * D_IN + k) * H_DIM + n];
        g_ug[b * H_DIM + n] = acc;
    }
}

// ---------------------------------------------------------------------------
// GEMM with ldmatrix-fed m16n8k8 tf32, 3-stage cp.async pipeline,
// ONE __syncthreads per k-tile (staging issued before compute).
// MODE 1: h = relu(cat(src,dest,edge)@W1abc + ug[bidx]) -> g_h (tf32-rounded)
// MODE 2: out = g_h @ W2 + b2
// ---------------------------------------------------------------------------
template <int MODE>
__global__ void __launch_bounds__(256, 2)
mlp_gemm(const float* __restrict__ A0, const float* __restrict__ A1,
         const float* __restrict__ A2, const float* __restrict__ bias2,
         float* __restrict__ out, int E) {
    extern __shared__ float smem[];
    const uint32_t sbase = (uint32_t)__cvta_generic_to_shared(smem);

    const int e0 = blockIdx.y * BM;
    const int n0 = blockIdx.x * BN;

    const int tid  = threadIdx.x;
    const int lane = tid & 31;
    const int warp = tid >> 5;
    const int wRow = (warp >> 1) * 32;     // warp m-offset (4 m-groups)
    const int wCol = (warp & 1) * 64;      // warp n-offset (2 n-groups)

    float c[2][8][4];
    #pragma unroll
    for (int mt = 0; mt < 2; mt++)
        #pragma unroll
        for (int nt = 0; nt < 8; nt++)
            #pragma unroll
            for (int i = 0; i < 4; i++) c[mt][nt][i] = 0.f;

    // ldmatrix lane->address maps (byte offsets within a tile)
    uint32_t aOff[2];
    #pragma unroll
    for (int mt = 0; mt < 2; mt++) {
        int r  = wRow + mt * 16 + (lane & 15);
        int cs = (lane >> 4) * 4;
        aOff[mt] = (uint32_t)(r * TSTRIDE + cs) * 4;
    }
    uint32_t bOff[4];
    #pragma unroll
    for (int pp = 0; pp < 4; pp++) {
        int r  = wCol + pp * 16 + ((lane >> 4) ? 8 : 0) + (lane & 7);
        int cs = ((lane >> 3) & 1) * 4;
        bOff[pp] = (uint32_t)(r * TSTRIDE + cs) * 4;
    }

    // cp.async staging map: both tiles 128 rows x 8 chunks of 16B
    const int sRow = tid >> 1;             // 0..127
    const int sChk = (tid & 1) * 4;        // chunk base; +i gives 0..7

    constexpr int KT   = (MODE == 1) ? (3 * D_IN) / BK : H_DIM / BK;   // 24 / 16
    constexpr int KDIM = (MODE == 1) ? (3 * D_IN) : H_DIM;

    auto stage = [&](int kt, int slot) {
        const int kg = kt * BK;
        const uint32_t sA = sbase + (uint32_t)(slot * STAGE_FLOATS) * 4;
        const uint32_t sB = sA + TILE_FLOATS * 4;
        const float* Ap;
        int kin;
        if (MODE == 1) {
            Ap  = (kg < 256) ? A0 : (kg < 512) ? A1 : A2;
            kin = kg & 255;
        } else {
            Ap  = g_h;
            kin = kg;
        }
        const float* Bp = (MODE == 1) ? g_w1t : g_w2t;
        #pragma unroll
        for (int i = 0; i < 4; i++) {
            const int c4 = sChk + i;
            const uint32_t so = (uint32_t)(sRow * TSTRIDE + c4 * 4) * 4;
            if (MODE == 1) {
                const int e = e0 + sRow;
                const int ec = (e < E) ? e : 0;
                cp16(sA + so, Ap + (size_t)ec * D_IN + kin + c4 * 4, (e < E) ? 16u : 0u);
            } else {
                cp16(sA + so, Ap + (size_t)(e0 + sRow) * H_DIM + kin + c4 * 4, 16u);
            }
            cp16(sB + so, Bp + (size_t)(n0 + sRow) * KDIM + kg + c4 * 4, 16u);
        }
        cp_commit();
    };

    // Prologue: two tiles in flight
    stage(0, 0);
    stage(1, 1);

    int rd = 0;                                // slot holding tile kt
    for (int kt = 0; kt < KT; kt++) {
        if (kt + 1 < KT) cp_wait<1>();         // tile kt landed (>=1 newer pending)
        else             cp_wait<0>();
        __syncthreads();                       // all writes for tile kt visible;
                                               // everyone done reading slot (kt-1)%S

        // Issue next stage BEFORE compute: overlaps LDGSTS issue + flight with MMAs.
        // Writes slot (kt+2)%S, last read in iteration kt-1 -> WAR safe via the sync.
        int wr = rd + 2; if (wr >= STAGES) wr -= STAGES;
        if (kt + 2 < KT) stage(kt + 2, wr);

        const uint32_t sA = sbase + (uint32_t)(rd * STAGE_FLOATS) * 4;
        const uint32_t sB = sA + TILE_FLOATS * 4;

        #pragma unroll
        for (int kk = 0; kk < BK; kk += 8) {
            uint32_t a[2][4];
            uint32_t b[4][4];
            #pragma unroll
            for (int mt = 0; mt < 2; mt++) {
                ldsm4(a[mt], sA + aOff[mt] + kk * 4);
                if (MODE == 1) {
                    #pragma unroll
                    for (int j = 0; j < 4; j++)
                        a[mt][j] = tf32r(__uint_as_float(a[mt][j]));
                }
            }
            #pragma unroll
            for (int pp = 0; pp < 4; pp++)
                ldsm4(b[pp], sB + bOff[pp] + kk * 4);

            #pragma unroll
            for (int mt = 0; mt < 2; mt++)
                #pragma unroll
                for (int nt = 0; nt < 8; nt++)
                    mma_tf32(c[mt][nt], a[mt], &b[nt >> 1][(nt & 1) * 2]);
        }

        rd = rd + 1; if (rd >= STAGES) rd -= STAGES;
    }

    // Epilogue
    #pragma unroll
    for (int mt = 0; mt < 2; mt++) {
        #pragma unroll
        for (int half = 0; half < 2; half++) {
            int r = wRow + mt * 16 + (lane >> 2) + half * 8;
            int e = e0 + r;
            if (e >= E) continue;
            if (MODE == 1) {
                int bg = g_bidx[e];
                const float* ugr = &g_ug[(size_t)bg * H_DIM + n0];
                float*       hr  = &g_h[(size_t)e * H_DIM + n0];
                #pragma unroll
                for (int nt = 0; nt < 8; nt++) {
                    int col = wCol + nt * 8 + (lane & 3) * 2;
                    float2 g = *(const float2*)&ugr[col];
                    float2 o;
                    o.x = to_tf32(fmaxf(c[mt][nt][half * 2 + 0] + g.x, 0.f));
                    o.y = to_tf32(fmaxf(c[mt][nt][half * 2 + 1] + g.y, 0.f));
                    *(float2*)&hr[col] = o;
                }
            } else {
                float* orow = &out[(size_t)e * DO_DIM + n0];
                #pragma unroll
                for (int nt = 0; nt < 8; nt++) {
                    int col = wCol + nt * 8 + (lane & 3) * 2;
                    float2 bb = *(const float2*)&bias2[col + n0];
                    float2 o;
                    o.x = c[mt][nt][half * 2 + 0] + bb.x;
                    o.y = c[mt][nt][half * 2 + 1] + bb.y;
                    *(float2*)&orow[col] = o;
                }
            }
        }
    }
}

// ---------------------------------------------------------------------------
// Inputs (metadata order): src, dest, edge_attr, u, batch, W1, b1, W2, b2
// ---------------------------------------------------------------------------
extern "C" void kernel_launch(void* const* d_in, const int* in_sizes, int n_in,
                              void* d_out, int out_size) {
    const float* src   = (const float*)d_in[0];
    const float* dest  = (const float*)d_in[1];
    const float* edge  = (const float*)d_in[2];
    const float* u     = (const float*)d_in[3];
    const int*   batch = (const int*)d_in[4];
    const float* W1    = (const float*)d_in[5];
    const float* b1    = (const float*)d_in[6];
    const float* W2    = (const float*)d_in[7];
    const float* b2    = (const float*)d_in[8];
    float* out = (float*)d_out;

    const int E  = in_sizes[4];
    const int EB = (E + BM - 1) / BM;

    static bool attr_set = false;
    if (!attr_set) {
        cudaFuncSetAttribute(mlp_gemm<1>, cudaFuncAttributeMaxDynamicSharedMemorySize, SMEM_BYTES);
        cudaFuncSetAttribute(mlp_gemm<2>, cudaFuncAttributeMaxDynamicSharedMemorySize, SMEM_BYTES);
        attr_set = true;
    }

    bidx_kernel<<<256, 256>>>(batch, E);
    prep_w<<<256, 256>>>(W1, W2);
    ug_kernel<<<B_GR, 256>>>(u, W1, b1);

    dim3 g1(H_DIM / BN, EB);     // n-tiles adjacent -> A rows reused in L2
    mlp_gemm<1><<<g1, 256, SMEM_BYTES>>>(src, dest, edge, nullptr, nullptr, E);

    dim3 g2(DO_DIM / BN, EB);
    mlp_gemm<2><<<g2, 256, SMEM_BYTES>>>(nullptr, nullptr, nullptr, b2, out, E);
}

// round 11
// speedup vs baseline: 1.4850x; 1.1082x over previous
#include <cuda_runtime.h>
#include <cstdint>
#include <cstddef>

#define D_IN    256
#define H_DIM   512
#define DO_DIM  256
#define B_GR    64

#define BM  64
#define BN  128
#define BK  32
#define E_MAX 200064

#define A_BYTES (BM * BK * 4)                // 8192
#define B_BYTES (BN * BK * 4)                // 16384
#define STAGE_BYTES (A_BYTES + B_BYTES)      // 24576
#define STAGES 3
#define SMEM_BYTES (STAGES * STAGE_BYTES)    // 73728 -> 3 CTAs/SM

// Allocation-free scratch
__device__ float g_h[(size_t)E_MAX * H_DIM];         // tf32-rounded activations
__device__ float g_ug[B_GR * H_DIM];
__device__ int   g_bidx[E_MAX];
__device__ float g_w1t[(size_t)H_DIM * (3 * D_IN)];  // W1^T [n=512][k=768], tf32-rounded
__device__ float g_w2t[(size_t)DO_DIM * H_DIM];      // W2^T [n=256][k=512], tf32-rounded

__device__ __forceinline__ float to_tf32(float x) {
    uint32_t u;
    asm("cvt.rna.tf32.f32 %0, %1;" : "=r"(u) : "f"(x));
    return __uint_as_float(u);
}
__device__ __forceinline__ uint32_t tf32r(float x) {
    uint32_t u;
    asm("cvt.rna.tf32.f32 %0, %1;" : "=r"(u) : "f"(x));
    return u;
}
__device__ __forceinline__ void mma_tf32(float* c, const uint32_t* a, const uint32_t* b) {
    asm volatile(
        "mma.sync.aligned.m16n8k8.row.col.f32.tf32.tf32.f32 "
        "{%0,%1,%2,%3}, {%4,%5,%6,%7}, {%8,%9}, {%0,%1,%2,%3};\n"
        : "+f"(c[0]), "+f"(c[1]), "+f"(c[2]), "+f"(c[3])
        : "r"(a[0]), "r"(a[1]), "r"(a[2]), "r"(a[3]), "r"(b[0]), "r"(b[1]));
}
__device__ __forceinline__ void ldsm4(uint32_t* r, uint32_t saddr) {
    asm volatile("ldmatrix.sync.aligned.m8n8.x4.shared.b16 {%0,%1,%2,%3}, [%4];"
                 : "=r"(r[0]), "=r"(r[1]), "=r"(r[2]), "=r"(r[3]) : "r"(saddr));
}
__device__ __forceinline__ void cp16(uint32_t saddr, const void* gaddr, uint32_t sz) {
    asm volatile("cp.async.cg.shared.global [%0], [%1], 16, %2;\n"
                 :: "r"(saddr), "l"(gaddr), "r"(sz));
}
__device__ __forceinline__ void cp_commit() { asm volatile("cp.async.commit_group;\n"); }
template <int N>
__device__ __forceinline__ void cp_wait() { asm volatile("cp.async.wait_group %0;\n" :: "n"(N)); }

// ---------------------------------------------------------------------------
// batch index normalization (int32 or int64 source) -> g_bidx
// ---------------------------------------------------------------------------
__global__ void bidx_kernel(const int* __restrict__ batch32, int E) {
    const int tid = threadIdx.x;
    __shared__ int s_is64;
    bool ok = true;
    if (tid < 128) {
        int lo = batch32[2 * tid];
        int hi = batch32[2 * tid + 1];
        ok = (hi == 0) && (lo >= 0) && (lo < B_GR);
    }
    unsigned m = __ballot_sync(0xFFFFFFFFu, ok);
    __shared__ unsigned s_votes[8];
    if ((tid & 31) == 0) s_votes[tid >> 5] = m;
    __syncthreads();
    if (tid == 0) {
        bool all = true;
        for (int w = 0; w < 4; w++) all = all && (s_votes[w] == 0xFFFFFFFFu);
        s_is64 = all ? 1 : 0;
    }
    __syncthreads();
    const int is64 = s_is64;
    for (int e = blockIdx.x * blockDim.x + tid; e < E; e += gridDim.x * blockDim.x) {
        int v = is64 ? batch32[2 * e] : batch32[e];
        g_bidx[e] = v & (B_GR - 1);
    }
}

// ---------------------------------------------------------------------------
// Weight prep: transpose to [n][k] + tf32 round (once; ~2MB)
// ---------------------------------------------------------------------------
__global__ void prep_w(const float* __restrict__ W1, const float* __restrict__ W2) {
    const size_t n1 = (size_t)H_DIM * (3 * D_IN);
    const size_t n2 = (size_t)DO_DIM * H_DIM;
    for (size_t i = (size_t)blockIdx.x * blockDim.x + threadIdx.x; i < n1 + n2;
         i += (size_t)gridDim.x * blockDim.x) {
        if (i < n1) {
            int n = (int)(i / (3 * D_IN));
            int k = (int)(i % (3 * D_IN));
            g_w1t[i] = to_tf32(W1[(size_t)k * H_DIM + n]);
        } else {
            size_t o = i - n1;
            int n = (int)(o / H_DIM);
            int k = (int)(o % H_DIM);
            g_w2t[o] = to_tf32(W2[(size_t)k * DO_DIM + n]);
        }
    }
}

// ---------------------------------------------------------------------------
// ug[b][n] = b1[n] + sum_k u[b][k] * W1[768+k][n]  (fp32)
// ---------------------------------------------------------------------------
__global__ void ug_kernel(const float* __restrict__ u, const float* __restrict__ W1,
                          const float* __restrict__ b1) {
    int b = blockIdx.x;
    __shared__ float us[D_IN];
    for (int i = threadIdx.x; i < D_IN; i += blockDim.x) us[i] = u[b * D_IN + i];
    __syncthreads();
    for (int n = threadIdx.x; n < H_DIM; n += blockDim.x) {
        float acc = b1[n];
        #pragma unroll 8
        for (int k = 0; k < D_IN; k++)
            acc += us[k] * W1[(size_t)(3 * D_IN + k) * H_DIM + n];
        g_ug[b * H_DIM + n] = acc;
    }
}

// ---------------------------------------------------------------------------
// GEMM, CTA 64x128x32, 8 warps (2m x 4n, warp tile 32x32), 3-stage cp.async,
// XOR-swizzled 128B smem rows (no padding), targeted 3 CTAs/SM.
// MODE 1: h = relu(cat(src,dest,edge)@W1abc + ug[bidx]) -> g_h (tf32-rounded)
// MODE 2: out = g_h @ W2 + b2
// ---------------------------------------------------------------------------
template <int MODE>
__global__ void __launch_bounds__(256, 3)
mlp_gemm(const float* __restrict__ A0, const float* __restrict__ A1,
         const float* __restrict__ A2, const float* __restrict__ bias2,
         float* __restrict__ out, int E) {
    extern __shared__ float smem[];
    const uint32_t sbase = (uint32_t)__cvta_generic_to_shared(smem);

    const int e0 = blockIdx.y * BM;
    const int n0 = blockIdx.x * BN;

    const int tid  = threadIdx.x;
    const int lane = tid & 31;
    const int warp = tid >> 5;
    const int wRow = (warp >> 2) * 32;     // 2 m-groups
    const int wCol = (warp & 3) * 32;      // 4 n-groups

    float c[2][4][4];
    #pragma unroll
    for (int mt = 0; mt < 2; mt++)
        #pragma unroll
        for (int nt = 0; nt < 4; nt++)
            #pragma unroll
            for (int i = 0; i < 4; i++) c[mt][nt][i] = 0.f;

    // ldmatrix lane maps: row*128 bytes, swizzled 16B chunk = chunk ^ (row&7)
    int aR[2], aR7[2];
    #pragma unroll
    for (int mt = 0; mt < 2; mt++) {
        aR[mt]  = wRow + mt * 16 + (lane & 15);
        aR7[mt] = aR[mt] & 7;
    }
    const int aCb = lane >> 4;             // chunk base 0/1
    int bR[2], bR7[2];
    #pragma unroll
    for (int pp = 0; pp < 2; pp++) {
        bR[pp]  = wCol + pp * 16 + ((lane & 16) ? 8 : 0) + (lane & 7);
        bR7[pp] = bR[pp] & 7;
    }
    const int bCb = (lane >> 3) & 1;

    // cp.async staging maps
    const int aSRow = tid >> 2;            // 0..63
    const int aSC   = (tid & 3) * 2;       // +j (j<2) -> chunks 0..7
    const int bSRow = tid >> 1;            // 0..127
    const int bSC   = (tid & 1) * 4;       // +j (j<4)

    constexpr int KT   = (MODE == 1) ? (3 * D_IN) / BK : H_DIM / BK;   // 24 / 16
    constexpr int KDIM = (MODE == 1) ? (3 * D_IN) : H_DIM;

    auto stage = [&](int kt, int slot) {
        const int kg = kt * BK;
        const uint32_t sA = sbase + (uint32_t)slot * STAGE_BYTES;
        const uint32_t sB = sA + A_BYTES;
        const float* Ap;
        int kin;
        if (MODE == 1) {
            Ap  = (kg < 256) ? A0 : (kg < 512) ? A1 : A2;
            kin = kg & 255;
        } else {
            Ap  = g_h;
            kin = kg;
        }
        const float* Bp = (MODE == 1) ? g_w1t : g_w2t;
        #pragma unroll
        for (int j = 0; j < 2; j++) {
            const int ch = aSC + j;
            const uint32_t so = (uint32_t)(aSRow * 128 + (ch ^ (aSRow & 7)) * 16);
            if (MODE == 1) {
                const int e = e0 + aSRow;
                const int ec = (e < E) ? e : 0;
                cp16(sA + so, Ap + (size_t)ec * D_IN + kin + ch * 4, (e < E) ? 16u : 0u);
            } else {
                cp16(sA + so, Ap + (size_t)(e0 + aSRow) * H_DIM + kin + ch * 4, 16u);
            }
        }
        #pragma unroll
        for (int j = 0; j < 4; j++) {
            const int ch = bSC + j;
            const uint32_t so = (uint32_t)(bSRow * 128 + (ch ^ (bSRow & 7)) * 16);
            cp16(sB + so, Bp + (size_t)(n0 + bSRow) * KDIM + kg + ch * 4, 16u);
        }
        cp_commit();
    };

    // Prologue: two tiles in flight
    stage(0, 0);
    stage(1, 1);

    int rd = 0;
    for (int kt = 0; kt < KT; kt++) {
        if (kt + 1 < KT) cp_wait<1>();
        else             cp_wait<0>();
        __syncthreads();

        int wr = rd + 2; if (wr >= STAGES) wr -= STAGES;
        if (kt + 2 < KT) stage(kt + 2, wr);

        const uint32_t sA = sbase + (uint32_t)rd * STAGE_BYTES;
        const uint32_t sB = sA + A_BYTES;

        #pragma unroll
        for (int kk = 0; kk < BK; kk += 8) {
            const int kc = kk >> 2;                      // chunk base for this kk
            uint32_t a[2][4];
            uint32_t b[2][4];
            #pragma unroll
            for (int mt = 0; mt < 2; mt++) {
                ldsm4(a[mt], sA + (uint32_t)(aR[mt] * 128 + (((kc + aCb) ^ aR7[mt]) << 4)));
                if (MODE == 1) {
                    #pragma unroll
                    for (int j = 0; j < 4; j++)
                        a[mt][j] = tf32r(__uint_as_float(a[mt][j]));
                }
            }
            #pragma unroll
            for (int pp = 0; pp < 2; pp++)
                ldsm4(b[pp], sB + (uint32_t)(bR[pp] * 128 + (((kc + bCb) ^ bR7[pp]) << 4)));

            #pragma unroll
            for (int mt = 0; mt < 2; mt++)
                #pragma unroll
                for (int nt = 0; nt < 4; nt++)
                    mma_tf32(c[mt][nt], a[mt], &b[nt >> 1][(nt & 1) * 2]);
        }

        rd = rd + 1; if (rd >= STAGES) rd -= STAGES;
    }

    // Epilogue
    #pragma unroll
    for (int mt = 0; mt < 2; mt++) {
        #pragma unroll
        for (int half = 0; half < 2; half++) {
            int r = wRow + mt * 16 + (lane >> 2) + half * 8;
            int e = e0 + r;
            if (e >= E) continue;
            if (MODE == 1) {
                int bg = g_bidx[e];
                const float* ugr = &g_ug[(size_t)bg * H_DIM + n0];
                float*       hr  = &g_h[(size_t)e * H_DIM + n0];
                #pragma unroll
                for (int nt = 0; nt < 4; nt++) {
                    int col = wCol + nt * 8 + (lane & 3) * 2;
                    float2 g = *(const float2*)&ugr[col];
                    float2 o;
                    o.x = to_tf32(fmaxf(c[mt][nt][half * 2 + 0] + g.x, 0.f));
                    o.y = to_tf32(fmaxf(c[mt][nt][half * 2 + 1] + g.y, 0.f));
                    *(float2*)&hr[col] = o;
                }
            } else {
                float* orow = &out[(size_t)e * DO_DIM + n0];
                #pragma unroll
                for (int nt = 0; nt < 4; nt++) {
                    int col = wCol + nt * 8 + (lane & 3) * 2;
                    float2 bb = *(const float2*)&bias2[col + n0];
                    float2 o;
                    o.x = c[mt][nt][half * 2 + 0] + bb.x;
                    o.y = c[mt][nt][half * 2 + 1] + bb.y;
                    *(float2*)&orow[col] = o;
                }
            }
        }
    }
}

// ---------------------------------------------------------------------------
// Inputs (metadata order): src, dest, edge_attr, u, batch, W1, b1, W2, b2
// ---------------------------------------------------------------------------
extern "C" void kernel_launch(void* const* d_in, const int* in_sizes, int n_in,
                              void* d_out, int out_size) {
    const float* src   = (const float*)d_in[0];
    const float* dest  = (const float*)d_in[1];
    const float* edge  = (const float*)d_in[2];
    const float* u     = (const float*)d_in[3];
    const int*   batch = (const int*)d_in[4];
    const float* W1    = (const float*)d_in[5];
    const float* b1    = (const float*)d_in[6];
    const float* W2    = (const float*)d_in[7];
    const float* b2    = (const float*)d_in[8];
    float* out = (float*)d_out;

    const int E  = in_sizes[4];
    const int EB = (E + BM - 1) / BM;

    static bool attr_set = false;
    if (!attr_set) {
        cudaFuncSetAttribute(mlp_gemm<1>, cudaFuncAttributeMaxDynamicSharedMemorySize, SMEM_BYTES);
        cudaFuncSetAttribute(mlp_gemm<2>, cudaFuncAttributeMaxDynamicSharedMemorySize, SMEM_BYTES);
        attr_set = true;
    }

    bidx_kernel<<<256, 256>>>(batch, E);
    prep_w<<<256, 256>>>(W1, W2);
    ug_kernel<<<B_GR, 256>>>(u, W1, b1);

    dim3 g1(H_DIM / BN, EB);     // n-tiles adjacent -> A rows reused in L2
    mlp_gemm<1><<<g1, 256, SMEM_BYTES>>>(src, dest, edge, nullptr, nullptr, E);

    dim3 g2(DO_DIM / BN, EB);
    mlp_gemm<2><<<g2, 256, SMEM_BYTES>>>(nullptr, nullptr, nullptr, b2, out, E);
}

// round 12
// speedup vs baseline: 2.3795x; 1.6023x over previous
#include <cuda_runtime.h>
#include <cuda_fp16.h>
#include <cstdint>
#include <cstddef>

#define D_IN    256
#define H_DIM   512
#define DO_DIM  256
#define B_GR    64

#define BM  64
#define BN  128
#define BK  64
#define E_MAX 200064

#define A_BYTES (BM * BK * 2)                // 8192
#define B_BYTES (BN * BK * 2)                // 16384
#define STAGE_BYTES (A_BYTES + B_BYTES)      // 24576
#define STAGES 3
#define SMEM_BYTES (STAGES * STAGE_BYTES)    // 73728 -> 3 CTAs/SM

// Allocation-free scratch
__device__ __half g_x[(size_t)E_MAX * (3 * D_IN)];    // packed fp16 [src|dest|edge]
__device__ __half g_hh[(size_t)E_MAX * H_DIM];        // fp16 activations
__device__ float  g_ug[B_GR * H_DIM];
__device__ int    g_bidx[E_MAX];
__device__ __half g_w1h[(size_t)H_DIM * (3 * D_IN)];  // W1^T [n=512][k=768] fp16
__device__ __half g_w2h[(size_t)DO_DIM * H_DIM];      // W2^T [n=256][k=512] fp16

__device__ __forceinline__ void mma_f16(float* c, const uint32_t* a, const uint32_t* b) {
    asm volatile(
        "mma.sync.aligned.m16n8k16.row.col.f32.f16.f16.f32 "
        "{%0,%1,%2,%3}, {%4,%5,%6,%7}, {%8,%9}, {%0,%1,%2,%3};\n"
        : "+f"(c[0]), "+f"(c[1]), "+f"(c[2]), "+f"(c[3])
        : "r"(a[0]), "r"(a[1]), "r"(a[2]), "r"(a[3]), "r"(b[0]), "r"(b[1]));
}
__device__ __forceinline__ void ldsm4(uint32_t* r, uint32_t saddr) {
    asm volatile("ldmatrix.sync.aligned.m8n8.x4.shared.b16 {%0,%1,%2,%3}, [%4];"
                 : "=r"(r[0]), "=r"(r[1]), "=r"(r[2]), "=r"(r[3]) : "r"(saddr));
}
__device__ __forceinline__ void cp16(uint32_t saddr, const void* gaddr, uint32_t sz) {
    asm volatile("cp.async.cg.shared.global [%0], [%1], 16, %2;\n"
                 :: "r"(saddr), "l"(gaddr), "r"(sz));
}
__device__ __forceinline__ void cp_commit() { asm volatile("cp.async.commit_group;\n"); }
template <int N>
__device__ __forceinline__ void cp_wait() { asm volatile("cp.async.wait_group %0;\n" :: "n"(N)); }

// ---------------------------------------------------------------------------
// batch index normalization (int32 or int64 source) -> g_bidx
// ---------------------------------------------------------------------------
__global__ void bidx_kernel(const int* __restrict__ batch32, int E) {
    const int tid = threadIdx.x;
    __shared__ int s_is64;
    bool ok = true;
    if (tid < 128) {
        int lo = batch32[2 * tid];
        int hi = batch32[2 * tid + 1];
        ok = (hi == 0) && (lo >= 0) && (lo < B_GR);
    }
    unsigned m = __ballot_sync(0xFFFFFFFFu, ok);
    __shared__ unsigned s_votes[8];
    if ((tid & 31) == 0) s_votes[tid >> 5] = m;
    __syncthreads();
    if (tid == 0) {
        bool all = true;
        for (int w = 0; w < 4; w++) all = all && (s_votes[w] == 0xFFFFFFFFu);
        s_is64 = all ? 1 : 0;
    }
    __syncthreads();
    const int is64 = s_is64;
    for (int e = blockIdx.x * blockDim.x + tid; e < E; e += gridDim.x * blockDim.x) {
        int v = is64 ? batch32[2 * e] : batch32[e];
        g_bidx[e] = v & (B_GR - 1);
    }
}

// ---------------------------------------------------------------------------
// Pack src|dest|edge into contiguous fp16 rows g_x[e][768]
// ---------------------------------------------------------------------------
__global__ void prep_x(const float* __restrict__ src, const float* __restrict__ dest,
                       const float* __restrict__ edge, int E) {
    const int total = E * (D_IN / 4);
    for (int i = blockIdx.x * blockDim.x + threadIdx.x; i < total;
         i += gridDim.x * blockDim.x) {
        const int e = i >> 6;
        const int d = (i & 63) * 4;
        const size_t gs = (size_t)e * D_IN + d;
        const size_t go = (size_t)e * (3 * D_IN) + d;
        float4 v;
        v = *(const float4*)&src[gs];
        *(__half2*)&g_x[go + 0] = __floats2half2_rn(v.x, v.y);
        *(__half2*)&g_x[go + 2] = __floats2half2_rn(v.z, v.w);
        v = *(const float4*)&dest[gs];
        *(__half2*)&g_x[go + 256 + 0] = __floats2half2_rn(v.x, v.y);
        *(__half2*)&g_x[go + 256 + 2] = __floats2half2_rn(v.z, v.w);
        v = *(const float4*)&edge[gs];
        *(__half2*)&g_x[go + 512 + 0] = __floats2half2_rn(v.x, v.y);
        *(__half2*)&g_x[go + 512 + 2] = __floats2half2_rn(v.z, v.w);
    }
}

// ---------------------------------------------------------------------------
// Weight prep: transpose to [n][k] + fp16 round (once; small)
// ---------------------------------------------------------------------------
__global__ void prep_w(const float* __restrict__ W1, const float* __restrict__ W2) {
    const size_t n1 = (size_t)H_DIM * (3 * D_IN);
    const size_t n2 = (size_t)DO_DIM * H_DIM;
    for (size_t i = (size_t)blockIdx.x * blockDim.x + threadIdx.x; i < n1 + n2;
         i += (size_t)gridDim.x * blockDim.x) {
        if (i < n1) {
            int n = (int)(i / (3 * D_IN));
            int k = (int)(i % (3 * D_IN));
            g_w1h[i] = __float2half_rn(W1[(size_t)k * H_DIM + n]);
        } else {
            size_t o = i - n1;
            int n = (int)(o / H_DIM);
            int k = (int)(o % H_DIM);
            g_w2h[o] = __float2half_rn(W2[(size_t)k * DO_DIM + n]);
        }
    }
}

// ---------------------------------------------------------------------------
// ug[b][n] = b1[n] + sum_k u[b][k] * W1[768+k][n]  (fp32)
// ---------------------------------------------------------------------------
__global__ void ug_kernel(const float* __restrict__ u, const float* __restrict__ W1,
                          const float* __restrict__ b1) {
    int b = blockIdx.x;
    __shared__ float us[D_IN];
    for (int i = threadIdx.x; i < D_IN; i += blockDim.x) us[i] = u[b * D_IN + i];
    __syncthreads();
    for (int n = threadIdx.x; n < H_DIM; n += blockDim.x) {
        float acc = b1[n];
        #pragma unroll 8
        for (int k = 0; k < D_IN; k++)
            acc += us[k] * W1[(size_t)(3 * D_IN + k) * H_DIM + n];
        g_ug[b * H_DIM + n] = acc;
    }
}

// ---------------------------------------------------------------------------
// FP16 GEMM, CTA 64x128x64, 8 warps (2m x 4n, warp tile 32x32), m16n8k16,
// 3-stage cp.async, XOR-swizzled 128B rows, 3 CTAs/SM.
// MODE 1: h = relu(g_x@W1abc + ug[bidx]) -> g_hh (fp16)
// MODE 2: out = g_hh @ W2 + b2 (fp32 out)
// ---------------------------------------------------------------------------
template <int MODE>
__global__ void __launch_bounds__(256, 3)
mlp_gemm(const float* __restrict__ bias2, float* __restrict__ out, int E) {
    extern __shared__ __half smem[];
    const uint32_t sbase = (uint32_t)__cvta_generic_to_shared(smem);

    const int e0 = blockIdx.y * BM;
    const int n0 = blockIdx.x * BN;

    const int tid  = threadIdx.x;
    const int lane = tid & 31;
    const int warp = tid >> 5;
    const int wRow = (warp >> 2) * 32;     // 2 m-groups
    const int wCol = (warp & 3) * 32;      // 4 n-groups

    float c[2][4][4];
    #pragma unroll
    for (int mt = 0; mt < 2; mt++)
        #pragma unroll
        for (int nt = 0; nt < 4; nt++)
            #pragma unroll
            for (int i = 0; i < 4; i++) c[mt][nt][i] = 0.f;

    // ldmatrix lane maps (rows are 128B = 64 halves; swizzled chunk = ch ^ (row&7))
    int aR[2], aR7[2];
    #pragma unroll
    for (int mt = 0; mt < 2; mt++) {
        aR[mt]  = wRow + mt * 16 + (lane & 15);
        aR7[mt] = aR[mt] & 7;
    }
    const int aCb = lane >> 4;             // +0 / +1 chunk
    int bR[2], bR7[2];
    #pragma unroll
    for (int pp = 0; pp < 2; pp++) {
        bR[pp]  = wCol + pp * 16 + ((lane & 16) ? 8 : 0) + (lane & 7);
        bR7[pp] = bR[pp] & 7;
    }
    const int bCb = (lane >> 3) & 1;

    // cp.async staging maps (chunks are 16B = 8 halves)
    const int aSRow = tid >> 2;            // 0..63
    const int aSC   = (tid & 3) * 2;       // +j (j<2) -> chunks 0..7
    const int bSRow = tid >> 1;            // 0..127
    const int bSC   = (tid & 1) * 4;       // +j (j<4)

    constexpr int KT   = (MODE == 1) ? (3 * D_IN) / BK : H_DIM / BK;   // 12 / 8
    constexpr int KDIM = (MODE == 1) ? (3 * D_IN) : H_DIM;

    const __half* Ap = (MODE == 1) ? g_x : g_hh;
    const __half* Bp = (MODE == 1) ? g_w1h : g_w2h;

    auto stage = [&](int kt, int slot) {
        const int kg = kt * BK;
        const uint32_t sA = sbase + (uint32_t)slot * STAGE_BYTES;
        const uint32_t sB = sA + A_BYTES;
        #pragma unroll
        for (int j = 0; j < 2; j++) {
            const int ch = aSC + j;
            const uint32_t so = (uint32_t)(aSRow * 128 + (ch ^ (aSRow & 7)) * 16);
            const int e = e0 + aSRow;
            const int ec = (e < E) ? e : 0;
            cp16(sA + so, Ap + (size_t)ec * KDIM + kg + ch * 8, (e < E) ? 16u : 0u);
        }
        #pragma unroll
        for (int j = 0; j < 4; j++) {
            const int ch = bSC + j;
            const uint32_t so = (uint32_t)(bSRow * 128 + (ch ^ (bSRow & 7)) * 16);
            cp16(sB + so, Bp + (size_t)(n0 + bSRow) * KDIM + kg + ch * 8, 16u);
        }
        cp_commit();
    };

    // Prologue: two tiles in flight
    stage(0, 0);
    stage(1, 1);

    int rd = 0;
    for (int kt = 0; kt < KT; kt++) {
        if (kt + 1 < KT) cp_wait<1>();
        else             cp_wait<0>();
        __syncthreads();

        int wr = rd + 2; if (wr >= STAGES) wr -= STAGES;
        if (kt + 2 < KT) stage(kt + 2, wr);

        const uint32_t sA = sbase + (uint32_t)rd * STAGE_BYTES;
        const uint32_t sB = sA + A_BYTES;

        #pragma unroll
        for (int t = 0; t < 4; t++) {              // 4 x k16 within BK=64
            const int kc = t * 2;                  // 16B-chunk base
            uint32_t a[2][4];
            uint32_t b[2][4];
            #pragma unroll
            for (int mt = 0; mt < 2; mt++)
                ldsm4(a[mt], sA + (uint32_t)(aR[mt] * 128 + (((kc + aCb) ^ aR7[mt]) << 4)));
            #pragma unroll
            for (int pp = 0; pp < 2; pp++)
                ldsm4(b[pp], sB + (uint32_t)(bR[pp] * 128 + (((kc + bCb) ^ bR7[pp]) << 4)));

            #pragma unroll
            for (int mt = 0; mt < 2; mt++)
                #pragma unroll
                for (int nt = 0; nt < 4; nt++)
                    mma_f16(c[mt][nt], a[mt], &b[nt >> 1][(nt & 1) * 2]);
        }

        rd = rd + 1; if (rd >= STAGES) rd -= STAGES;
    }

    // Epilogue (C frag: lane -> row = base + lane>>2 (+8), cols = 2*(lane&3))
    #pragma unroll
    for (int mt = 0; mt < 2; mt++) {
        #pragma unroll
        for (int half = 0; half < 2; half++) {
            int r = wRow + mt * 16 + (lane >> 2) + half * 8;
            int e = e0 + r;
            if (e >= E) continue;
            if (MODE == 1) {
                int bg = g_bidx[e];
                const float* ugr = &g_ug[(size_t)bg * H_DIM + n0];
                __half*      hr  = &g_hh[(size_t)e * H_DIM + n0];
                #pragma unroll
                for (int nt = 0; nt < 4; nt++) {
                    int col = wCol + nt * 8 + (lane & 3) * 2;
                    float2 g = *(const float2*)&ugr[col];
                    float ox = fmaxf(c[mt][nt][half * 2 + 0] + g.x, 0.f);
                    float oy = fmaxf(c[mt][nt][half * 2 + 1] + g.y, 0.f);
                    *(__half2*)&hr[col] = __floats2half2_rn(ox, oy);
                }
            } else {
                float* orow = &out[(size_t)e * DO_DIM + n0];
                #pragma unroll
                for (int nt = 0; nt < 4; nt++) {
                    int col = wCol + nt * 8 + (lane & 3) * 2;
                    float2 bb = *(const float2*)&bias2[col + n0];
                    float2 o;
                    o.x = c[mt][nt][half * 2 + 0] + bb.x;
                    o.y = c[mt][nt][half * 2 + 1] + bb.y;
                    *(float2*)&orow[col] = o;
                }
            }
        }
    }
}

// ---------------------------------------------------------------------------
// Inputs (metadata order): src, dest, edge_attr, u, batch, W1, b1, W2, b2
// ---------------------------------------------------------------------------
extern "C" void kernel_launch(void* const* d_in, const int* in_sizes, int n_in,
                              void* d_out, int out_size) {
    const float* src   = (const float*)d_in[0];
    const float* dest  = (const float*)d_in[1];
    const float* edge  = (const float*)d_in[2];
    const float* u     = (const float*)d_in[3];
    const int*   batch = (const int*)d_in[4];
    const float* W1    = (const float*)d_in[5];
    const float* b1    = (const float*)d_in[6];
    const float* W2    = (const float*)d_in[7];
    const float* b2    = (const float*)d_in[8];
    float* out = (float*)d_out;

    const int E  = in_sizes[4];
    const int EB = (E + BM - 1) / BM;

    static bool attr_set = false;
    if (!attr_set) {
        cudaFuncSetAttribute(mlp_gemm<1>, cudaFuncAttributeMaxDynamicSharedMemorySize, SMEM_BYTES);
        cudaFuncSetAttribute(mlp_gemm<2>, cudaFuncAttributeMaxDynamicSharedMemorySize, SMEM_BYTES);
        attr_set = true;
    }

    bidx_kernel<<<256, 256>>>(batch, E);
    prep_x<<<2048, 256>>>(src, dest, edge, E);
    prep_w<<<256, 256>>>(W1, W2);
    ug_kernel<<<B_GR, 256>>>(u, W1, b1);

    dim3 g1(H_DIM / BN, EB);     // n-tiles adjacent -> A rows reused in L2
    mlp_gemm<1><<<g1, 256, SMEM_BYTES>>>(nullptr, nullptr, E);

    dim3 g2(DO_DIM / BN, EB);
    mlp_gemm<2><<<g2, 256, SMEM_BYTES>>>(b2, out, E);
}

// round 13
// speedup vs baseline: 2.4345x; 1.0231x over previous
#include <cuda_runtime.h>
#include <cuda_fp16.h>
#include <cstdint>
#include <cstddef>

#define D_IN    256
#define H_DIM   512
#define DO_DIM  256
#define B_GR    64

#define BM  64
#define BN  128
#define BK  64
#define E_MAX 200064

#define A_BYTES (BM * BK * 2)                // 8192
#define B_BYTES (BN * BK * 2)                // 16384
#define STAGE_BYTES (A_BYTES + B_BYTES)      // 24576
#define STAGES 2
#define SMEM_BYTES (STAGES * STAGE_BYTES)    // 49152 -> 4 CTAs/SM

// Allocation-free scratch
__device__ __half g_x[(size_t)E_MAX * (3 * D_IN)];    // packed fp16 [src|dest|edge]
__device__ __half g_hh[(size_t)E_MAX * H_DIM];        // fp16 activations
__device__ float  g_ug[B_GR * H_DIM];
__device__ int    g_bidx[E_MAX];
__device__ __half g_w1h[(size_t)H_DIM * (3 * D_IN)];  // W1^T [n=512][k=768] fp16
__device__ __half g_w2h[(size_t)DO_DIM * H_DIM];      // W2^T [n=256][k=512] fp16

__device__ __forceinline__ void mma_f16(float* c, const uint32_t* a, const uint32_t* b) {
    asm volatile(
        "mma.sync.aligned.m16n8k16.row.col.f32.f16.f16.f32 "
        "{%0,%1,%2,%3}, {%4,%5,%6,%7}, {%8,%9}, {%0,%1,%2,%3};\n"
        : "+f"(c[0]), "+f"(c[1]), "+f"(c[2]), "+f"(c[3])
        : "r"(a[0]), "r"(a[1]), "r"(a[2]), "r"(a[3]), "r"(b[0]), "r"(b[1]));
}
__device__ __forceinline__ void ldsm4(uint32_t* r, uint32_t saddr) {
    asm volatile("ldmatrix.sync.aligned.m8n8.x4.shared.b16 {%0,%1,%2,%3}, [%4];"
                 : "=r"(r[0]), "=r"(r[1]), "=r"(r[2]), "=r"(r[3]) : "r"(saddr));
}
__device__ __forceinline__ void cp16(uint32_t saddr, const void* gaddr, uint32_t sz) {
    asm volatile("cp.async.cg.shared.global [%0], [%1], 16, %2;\n"
                 :: "r"(saddr), "l"(gaddr), "r"(sz));
}
__device__ __forceinline__ void cp_commit() { asm volatile("cp.async.commit_group;\n"); }
template <int N>
__device__ __forceinline__ void cp_wait() { asm volatile("cp.async.wait_group %0;\n" :: "n"(N)); }

// ---------------------------------------------------------------------------
// batch index normalization (int32 or int64 source) -> g_bidx
// ---------------------------------------------------------------------------
__global__ void bidx_kernel(const int* __restrict__ batch32, int E) {
    const int tid = threadIdx.x;
    __shared__ int s_is64;
    bool ok = true;
    if (tid < 128) {
        int lo = batch32[2 * tid];
        int hi = batch32[2 * tid + 1];
        ok = (hi == 0) && (lo >= 0) && (lo < B_GR);
    }
    unsigned m = __ballot_sync(0xFFFFFFFFu, ok);
    __shared__ unsigned s_votes[8];
    if ((tid & 31) == 0) s_votes[tid >> 5] = m;
    __syncthreads();
    if (tid == 0) {
        bool all = true;
        for (int w = 0; w < 4; w++) all = all && (s_votes[w] == 0xFFFFFFFFu);
        s_is64 = all ? 1 : 0;
    }
    __syncthreads();
    const int is64 = s_is64;
    for (int e = blockIdx.x * blockDim.x + tid; e < E; e += gridDim.x * blockDim.x) {
        int v = is64 ? batch32[2 * e] : batch32[e];
        g_bidx[e] = v & (B_GR - 1);
    }
}

// ---------------------------------------------------------------------------
// Pack src|dest|edge into contiguous fp16 rows g_x[e][768]
// ---------------------------------------------------------------------------
__global__ void prep_x(const float* __restrict__ src, const float* __restrict__ dest,
                       const float* __restrict__ edge, int E) {
    const int total = E * (D_IN / 4);
    for (int i = blockIdx.x * blockDim.x + threadIdx.x; i < total;
         i += gridDim.x * blockDim.x) {
        const int e = i >> 6;
        const int d = (i & 63) * 4;
        const size_t gs = (size_t)e * D_IN + d;
        const size_t go = (size_t)e * (3 * D_IN) + d;
        float4 v;
        v = *(const float4*)&src[gs];
        *(__half2*)&g_x[go + 0] = __floats2half2_rn(v.x, v.y);
        *(__half2*)&g_x[go + 2] = __floats2half2_rn(v.z, v.w);
        v = *(const float4*)&dest[gs];
        *(__half2*)&g_x[go + 256 + 0] = __floats2half2_rn(v.x, v.y);
        *(__half2*)&g_x[go + 256 + 2] = __floats2half2_rn(v.z, v.w);
        v = *(const float4*)&edge[gs];
        *(__half2*)&g_x[go + 512 + 0] = __floats2half2_rn(v.x, v.y);
        *(__half2*)&g_x[go + 512 + 2] = __floats2half2_rn(v.z, v.w);
    }
}

// ---------------------------------------------------------------------------
// Weight prep: transpose to [n][k] + fp16 round (once; small)
// ---------------------------------------------------------------------------
__global__ void prep_w(const float* __restrict__ W1, const float* __restrict__ W2) {
    const size_t n1 = (size_t)H_DIM * (3 * D_IN);
    const size_t n2 = (size_t)DO_DIM * H_DIM;
    for (size_t i = (size_t)blockIdx.x * blockDim.x + threadIdx.x; i < n1 + n2;
         i += (size_t)gridDim.x * blockDim.x) {
        if (i < n1) {
            int n = (int)(i / (3 * D_IN));
            int k = (int)(i % (3 * D_IN));
            g_w1h[i] = __float2half_rn(W1[(size_t)k * H_DIM + n]);
        } else {
            size_t o = i - n1;
            int n = (int)(o / H_DIM);
            int k = (int)(o % H_DIM);
            g_w2h[o] = __float2half_rn(W2[(size_t)k * DO_DIM + n]);
        }
    }
}

// ---------------------------------------------------------------------------
// ug[b][n] = b1[n] + sum_k u[b][k] * W1[768+k][n]  (fp32)
// grid (B_GR, 4) x 128 threads: block = (graph b, n-chunk of 128)
// ---------------------------------------------------------------------------
__global__ void ug_kernel(const float* __restrict__ u, const float* __restrict__ W1,
                          const float* __restrict__ b1) {
    const int b = blockIdx.x;
    const int n = blockIdx.y * 128 + threadIdx.x;
    __shared__ float us[D_IN];
    for (int i = threadIdx.x; i < D_IN; i += 128) us[i] = u[b * D_IN + i];
    __syncthreads();
    float acc = b1[n];
    #pragma unroll 8
    for (int k = 0; k < D_IN; k++)
        acc += us[k] * W1[(size_t)(3 * D_IN + k) * H_DIM + n];
    g_ug[b * H_DIM + n] = acc;
}

// ---------------------------------------------------------------------------
// FP16 GEMM, CTA 64x128x64, 8 warps (2m x 4n, warp tile 32x32), m16n8k16,
// 2-stage cp.async (two-sync loop), XOR-swizzled 128B rows, 4 CTAs/SM.
// MODE 1: h = relu(g_x@W1abc + ug[bidx]) -> g_hh (fp16)
// MODE 2: out = g_hh @ W2 + b2 (fp32 out)
// ---------------------------------------------------------------------------
template <int MODE>
__global__ void __launch_bounds__(256, 4)
mlp_gemm(const float* __restrict__ bias2, float* __restrict__ out, int E) {
    extern __shared__ __half smem[];
    const uint32_t sbase = (uint32_t)__cvta_generic_to_shared(smem);

    const int e0 = blockIdx.y * BM;
    const int n0 = blockIdx.x * BN;

    const int tid  = threadIdx.x;
    const int lane = tid & 31;
    const int warp = tid >> 5;
    const int wRow = (warp >> 2) * 32;     // 2 m-groups
    const int wCol = (warp & 3) * 32;      // 4 n-groups

    float c[2][4][4];
    #pragma unroll
    for (int mt = 0; mt < 2; mt++)
        #pragma unroll
        for (int nt = 0; nt < 4; nt++)
            #pragma unroll
            for (int i = 0; i < 4; i++) c[mt][nt][i] = 0.f;

    // ldmatrix lane maps (rows are 128B = 64 halves; swizzled chunk = ch ^ (row&7))
    int aR[2], aR7[2];
    #pragma unroll
    for (int mt = 0; mt < 2; mt++) {
        aR[mt]  = wRow + mt * 16 + (lane & 15);
        aR7[mt] = aR[mt] & 7;
    }
    const int aCb = lane >> 4;             // +0 / +1 chunk
    int bR[2], bR7[2];
    #pragma unroll
    for (int pp = 0; pp < 2; pp++) {
        bR[pp]  = wCol + pp * 16 + ((lane & 16) ? 8 : 0) + (lane & 7);
        bR7[pp] = bR[pp] & 7;
    }
    const int bCb = (lane >> 3) & 1;

    // cp.async staging maps (chunks are 16B = 8 halves)
    const int aSRow = tid >> 2;            // 0..63
    const int aSC   = (tid & 3) * 2;       // +j (j<2) -> chunks 0..7
    const int bSRow = tid >> 1;            // 0..127
    const int bSC   = (tid & 1) * 4;       // +j (j<4)

    constexpr int KT   = (MODE == 1) ? (3 * D_IN) / BK : H_DIM / BK;   // 12 / 8
    constexpr int KDIM = (MODE == 1) ? (3 * D_IN) : H_DIM;

    const __half* Ap = (MODE == 1) ? g_x : g_hh;
    const __half* Bp = (MODE == 1) ? g_w1h : g_w2h;

    auto stage = [&](int kt, int slot) {
        const int kg = kt * BK;
        const uint32_t sA = sbase + (uint32_t)slot * STAGE_BYTES;
        const uint32_t sB = sA + A_BYTES;
        #pragma unroll
        for (int j = 0; j < 2; j++) {
            const int ch = aSC + j;
            const uint32_t so = (uint32_t)(aSRow * 128 + (ch ^ (aSRow & 7)) * 16);
            const int e = e0 + aSRow;
            const int ec = (e < E) ? e : 0;
            cp16(sA + so, Ap + (size_t)ec * KDIM + kg + ch * 8, (e < E) ? 16u : 0u);
        }
        #pragma unroll
        for (int j = 0; j < 4; j++) {
            const int ch = bSC + j;
            const uint32_t so = (uint32_t)(bSRow * 128 + (ch ^ (bSRow & 7)) * 16);
            cp16(sB + so, Bp + (size_t)(n0 + bSRow) * KDIM + kg + ch * 8, 16u);
        }
        cp_commit();
    };

    stage(0, 0);

    for (int kt = 0; kt < KT; kt++) {
        // Issue next tile into the other slot (its readers finished at the
        // trailing sync of iteration kt-1), then wait for tile kt.
        if (kt + 1 < KT) { stage(kt + 1, (kt + 1) & 1); cp_wait<1>(); }
        else             { cp_wait<0>(); }
        __syncthreads();

        const uint32_t sA = sbase + (uint32_t)(kt & 1) * STAGE_BYTES;
        const uint32_t sB = sA + A_BYTES;

        #pragma unroll
        for (int t = 0; t < 4; t++) {              // 4 x k16 within BK=64
            const int kc = t * 2;                  // 16B-chunk base
            uint32_t a[2][4];
            uint32_t b[2][4];
            #pragma unroll
            for (int mt = 0; mt < 2; mt++)
                ldsm4(a[mt], sA + (uint32_t)(aR[mt] * 128 + (((kc + aCb) ^ aR7[mt]) << 4)));
            #pragma unroll
            for (int pp = 0; pp < 2; pp++)
                ldsm4(b[pp], sB + (uint32_t)(bR[pp] * 128 + (((kc + bCb) ^ bR7[pp]) << 4)));

            #pragma unroll
            for (int mt = 0; mt < 2; mt++)
                #pragma unroll
                for (int nt = 0; nt < 4; nt++)
                    mma_f16(c[mt][nt], a[mt], &b[nt >> 1][(nt & 1) * 2]);
        }
        __syncthreads();                           // WAR: slot kt&1 free for kt+2's stage
    }

    // Epilogue (C frag: lane -> row = base + lane>>2 (+8), cols = 2*(lane&3))
    #pragma unroll
    for (int mt = 0; mt < 2; mt++) {
        #pragma unroll
        for (int half = 0; half < 2; half++) {
            int r = wRow + mt * 16 + (lane >> 2) + half * 8;
            int e = e0 + r;
            if (e >= E) continue;
            if (MODE == 1) {
                int bg = g_bidx[e];
                const float* ugr = &g_ug[(size_t)bg * H_DIM + n0];
                __half*      hr  = &g_hh[(size_t)e * H_DIM + n0];
                #pragma unroll
                for (int nt = 0; nt < 4; nt++) {
                    int col = wCol + nt * 8 + (lane & 3) * 2;
                    float2 g = *(const float2*)&ugr[col];
                    float ox = fmaxf(c[mt][nt][half * 2 + 0] + g.x, 0.f);
                    float oy = fmaxf(c[mt][nt][half * 2 + 1] + g.y, 0.f);
                    *(__half2*)&hr[col] = __floats2half2_rn(ox, oy);
                }
            } else {
                float* orow = &out[(size_t)e * DO_DIM + n0];
                #pragma unroll
                for (int nt = 0; nt < 4; nt++) {
                    int col = wCol + nt * 8 + (lane & 3) * 2;
                    float2 bb = *(const float2*)&bias2[col + n0];
                    float2 o;
                    o.x = c[mt][nt][half * 2 + 0] + bb.x;
                    o.y = c[mt][nt][half * 2 + 1] + bb.y;
                    *(float2*)&orow[col] = o;
                }
            }
        }
    }
}

// ---------------------------------------------------------------------------
// Inputs (metadata order): src, dest, edge_attr, u, batch, W1, b1, W2, b2
// ---------------------------------------------------------------------------
extern "C" void kernel_launch(void* const* d_in, const int* in_sizes, int n_in,
                              void* d_out, int out_size) {
    const float* src   = (const float*)d_in[0];
    const float* dest  = (const float*)d_in[1];
    const float* edge  = (const float*)d_in[2];
    const float* u     = (const float*)d_in[3];
    const int*   batch = (const int*)d_in[4];
    const float* W1    = (const float*)d_in[5];
    const float* b1    = (const float*)d_in[6];
    const float* W2    = (const float*)d_in[7];
    const float* b2    = (const float*)d_in[8];
    float* out = (float*)d_out;

    const int E  = in_sizes[4];
    const int EB = (E + BM - 1) / BM;

    static bool attr_set = false;
    if (!attr_set) {
        cudaFuncSetAttribute(mlp_gemm<1>, cudaFuncAttributeMaxDynamicSharedMemorySize, SMEM_BYTES);
        cudaFuncSetAttribute(mlp_gemm<2>, cudaFuncAttributeMaxDynamicSharedMemorySize, SMEM_BYTES);
        attr_set = true;
    }

    bidx_kernel<<<256, 256>>>(batch, E);
    prep_x<<<2048, 256>>>(src, dest, edge, E);
    prep_w<<<256, 256>>>(W1, W2);
    ug_kernel<<<dim3(B_GR, 4), 128>>>(u, W1, b1);

    dim3 g1(H_DIM / BN, EB);     // n-tiles adjacent -> A rows reused in L2
    mlp_gemm<1><<<g1, 256, SMEM_BYTES>>>(nullptr, nullptr, E);

    dim3 g2(DO_DIM / BN, EB);
    mlp_gemm<2><<<g2, 256, SMEM_BYTES>>>(b2, out, E);
}

// round 14
// speedup vs baseline: 2.4485x; 1.0057x over previous
#include <cuda_runtime.h>
#include <cuda_fp16.h>
#include <cstdint>
#include <cstddef>

#define D_IN    256
#define H_DIM   512
#define DO_DIM  256
#define B_GR    64

#define BM  64
#define BN  128
#define BK  64
#define E_MAX 200064

#define A_BYTES (BM * BK * 2)                // 8192
#define B_BYTES (BN * BK * 2)                // 16384
#define STAGE_BYTES (A_BYTES + B_BYTES)      // 24576
#define STAGES 3
#define SMEM_BYTES (STAGES * STAGE_BYTES)    // 73728 -> 3 CTAs/SM

// Allocation-free scratch
__device__ __half g_x[(size_t)E_MAX * (3 * D_IN)];    // packed fp16 [src|dest|edge]
__device__ __half g_hh[(size_t)E_MAX * H_DIM];        // fp16 activations
__device__ float  g_ug[B_GR * H_DIM];
__device__ int    g_bidx[E_MAX];
__device__ __half g_w1h[(size_t)H_DIM * (3 * D_IN)];  // W1^T [n=512][k=768] fp16
__device__ __half g_w2h[(size_t)DO_DIM * H_DIM];      // W2^T [n=256][k=512] fp16

__device__ __forceinline__ void mma_f16(float* c, const uint32_t* a, const uint32_t* b) {
    asm volatile(
        "mma.sync.aligned.m16n8k16.row.col.f32.f16.f16.f32 "
        "{%0,%1,%2,%3}, {%4,%5,%6,%7}, {%8,%9}, {%0,%1,%2,%3};\n"
        : "+f"(c[0]), "+f"(c[1]), "+f"(c[2]), "+f"(c[3])
        : "r"(a[0]), "r"(a[1]), "r"(a[2]), "r"(a[3]), "r"(b[0]), "r"(b[1]));
}
__device__ __forceinline__ void ldsm4(uint32_t* r, uint32_t saddr) {
    asm volatile("ldmatrix.sync.aligned.m8n8.x4.shared.b16 {%0,%1,%2,%3}, [%4];"
                 : "=r"(r[0]), "=r"(r[1]), "=r"(r[2]), "=r"(r[3]) : "r"(saddr));
}
__device__ __forceinline__ void cp16(uint32_t saddr, const void* gaddr, uint32_t sz) {
    asm volatile("cp.async.cg.shared.global [%0], [%1], 16, %2;\n"
                 :: "r"(saddr), "l"(gaddr), "r"(sz));
}
__device__ __forceinline__ void cp_commit() { asm volatile("cp.async.commit_group;\n"); }
template <int N>
__device__ __forceinline__ void cp_wait() { asm volatile("cp.async.wait_group %0;\n" :: "n"(N)); }

// ---------------------------------------------------------------------------
// batch index normalization (int32 or int64 source) -> g_bidx
// ---------------------------------------------------------------------------
__global__ void bidx_kernel(const int* __restrict__ batch32, int E) {
    const int tid = threadIdx.x;
    __shared__ int s_is64;
    bool ok = true;
    if (tid < 128) {
        int lo = batch32[2 * tid];
        int hi = batch32[2 * tid + 1];
        ok = (hi == 0) && (lo >= 0) && (lo < B_GR);
    }
    unsigned m = __ballot_sync(0xFFFFFFFFu, ok);
    __shared__ unsigned s_votes[8];
    if ((tid & 31) == 0) s_votes[tid >> 5] = m;
    __syncthreads();
    if (tid == 0) {
        bool all = true;
        for (int w = 0; w < 4; w++) all = all && (s_votes[w] == 0xFFFFFFFFu);
        s_is64 = all ? 1 : 0;
    }
    __syncthreads();
    const int is64 = s_is64;
    for (int e = blockIdx.x * blockDim.x + tid; e < E; e += gridDim.x * blockDim.x) {
        int v = is64 ? batch32[2 * e] : batch32[e];
        g_bidx[e] = v & (B_GR - 1);
    }
}

// ---------------------------------------------------------------------------
// Pack src|dest|edge into contiguous fp16 rows g_x[e][768]
// ---------------------------------------------------------------------------
__global__ void prep_x(const float* __restrict__ src, const float* __restrict__ dest,
                       const float* __restrict__ edge, int E) {
    const int total = E * (D_IN / 4);
    for (int i = blockIdx.x * blockDim.x + threadIdx.x; i < total;
         i += gridDim.x * blockDim.x) {
        const int e = i >> 6;
        const int d = (i & 63) * 4;
        const size_t gs = (size_t)e * D_IN + d;
        const size_t go = (size_t)e * (3 * D_IN) + d;
        float4 v;
        v = *(const float4*)&src[gs];
        *(__half2*)&g_x[go + 0] = __floats2half2_rn(v.x, v.y);
        *(__half2*)&g_x[go + 2] = __floats2half2_rn(v.z, v.w);
        v = *(const float4*)&dest[gs];
        *(__half2*)&g_x[go + 256 + 0] = __floats2half2_rn(v.x, v.y);
        *(__half2*)&g_x[go + 256 + 2] = __floats2half2_rn(v.z, v.w);
        v = *(const float4*)&edge[gs];
        *(__half2*)&g_x[go + 512 + 0] = __floats2half2_rn(v.x, v.y);
        *(__half2*)&g_x[go + 512 + 2] = __floats2half2_rn(v.z, v.w);
    }
}

// ---------------------------------------------------------------------------
// Weight prep: transpose to [n][k] + fp16 round (once; small)
// ---------------------------------------------------------------------------
__global__ void prep_w(const float* __restrict__ W1, const float* __restrict__ W2) {
    const size_t n1 = (size_t)H_DIM * (3 * D_IN);
    const size_t n2 = (size_t)DO_DIM * H_DIM;
    for (size_t i = (size_t)blockIdx.x * blockDim.x + threadIdx.x; i < n1 + n2;
         i += (size_t)gridDim.x * blockDim.x) {
        if (i < n1) {
            int n = (int)(i / (3 * D_IN));
            int k = (int)(i % (3 * D_IN));
            g_w1h[i] = __float2half_rn(W1[(size_t)k * H_DIM + n]);
        } else {
            size_t o = i - n1;
            int n = (int)(o / H_DIM);
            int k = (int)(o % H_DIM);
            g_w2h[o] = __float2half_rn(W2[(size_t)k * DO_DIM + n]);
        }
    }
}

// ---------------------------------------------------------------------------
// ug[b][n] = b1[n] + sum_k u[b][k] * W1[768+k][n]  (fp32)
// ---------------------------------------------------------------------------
__global__ void ug_kernel(const float* __restrict__ u, const float* __restrict__ W1,
                          const float* __restrict__ b1) {
    const int b = blockIdx.x;
    const int n = blockIdx.y * 128 + threadIdx.x;
    __shared__ float us[D_IN];
    for (int i = threadIdx.x; i < D_IN; i += 128) us[i] = u[b * D_IN + i];
    __syncthreads();
    float acc = b1[n];
    #pragma unroll 8
    for (int k = 0; k < D_IN; k++)
        acc += us[k] * W1[(size_t)(3 * D_IN + k) * H_DIM + n];
    g_ug[b * H_DIM + n] = acc;
}

// ---------------------------------------------------------------------------
// FP16 GEMM, CTA 64x128x64, 8 warps (2m x 4n, warp tile 32x32), m16n8k16,
// 3-stage cp.async + single sync per tile + REGISTER FRAGMENT DOUBLE BUFFER,
// XOR-swizzled 128B rows, 3 CTAs/SM.
// MODE 1: h = relu(g_x@W1abc + ug[bidx]) -> g_hh (fp16)
// MODE 2: out = g_hh @ W2 + b2 (fp32 out)
// ---------------------------------------------------------------------------
template <int MODE>
__global__ void __launch_bounds__(256, 3)
mlp_gemm(const float* __restrict__ bias2, float* __restrict__ out, int E) {
    extern __shared__ __half smem[];
    const uint32_t sbase = (uint32_t)__cvta_generic_to_shared(smem);

    const int e0 = blockIdx.y * BM;
    const int n0 = blockIdx.x * BN;

    const int tid  = threadIdx.x;
    const int lane = tid & 31;
    const int warp = tid >> 5;
    const int wRow = (warp >> 2) * 32;     // 2 m-groups
    const int wCol = (warp & 3) * 32;      // 4 n-groups

    float c[2][4][4];
    #pragma unroll
    for (int mt = 0; mt < 2; mt++)
        #pragma unroll
        for (int nt = 0; nt < 4; nt++)
            #pragma unroll
            for (int i = 0; i < 4; i++) c[mt][nt][i] = 0.f;

    // ldmatrix lane maps (rows are 128B = 64 halves; swizzled chunk = ch ^ (row&7))
    int aR[2], aR7[2];
    #pragma unroll
    for (int mt = 0; mt < 2; mt++) {
        aR[mt]  = wRow + mt * 16 + (lane & 15);
        aR7[mt] = aR[mt] & 7;
    }
    const int aCb = lane >> 4;             // +0 / +1 chunk
    int bR[2], bR7[2];
    #pragma unroll
    for (int pp = 0; pp < 2; pp++) {
        bR[pp]  = wCol + pp * 16 + ((lane & 16) ? 8 : 0) + (lane & 7);
        bR7[pp] = bR[pp] & 7;
    }
    const int bCb = (lane >> 3) & 1;

    // cp.async staging maps (chunks are 16B = 8 halves)
    const int aSRow = tid >> 2;            // 0..63
    const int aSC   = (tid & 3) * 2;       // +j (j<2)
    const int bSRow = tid >> 1;            // 0..127
    const int bSC   = (tid & 1) * 4;       // +j (j<4)

    constexpr int KT   = (MODE == 1) ? (3 * D_IN) / BK : H_DIM / BK;   // 12 / 8
    constexpr int KDIM = (MODE == 1) ? (3 * D_IN) : H_DIM;

    const __half* Ap = (MODE == 1) ? g_x : g_hh;
    const __half* Bp = (MODE == 1) ? g_w1h : g_w2h;

    auto stage = [&](int kt, int slot) {
        const int kg = kt * BK;
        const uint32_t sA = sbase + (uint32_t)slot * STAGE_BYTES;
        const uint32_t sB = sA + A_BYTES;
        #pragma unroll
        for (int j = 0; j < 2; j++) {
            const int ch = aSC + j;
            const uint32_t so = (uint32_t)(aSRow * 128 + (ch ^ (aSRow & 7)) * 16);
            const int e = e0 + aSRow;
            const int ec = (e < E) ? e : 0;
            cp16(sA + so, Ap + (size_t)ec * KDIM + kg + ch * 8, (e < E) ? 16u : 0u);
        }
        #pragma unroll
        for (int j = 0; j < 4; j++) {
            const int ch = bSC + j;
            const uint32_t so = (uint32_t)(bSRow * 128 + (ch ^ (bSRow & 7)) * 16);
            cp16(sB + so, Bp + (size_t)(n0 + bSRow) * KDIM + kg + ch * 8, 16u);
        }
        cp_commit();
    };

    // Prologue: two tiles in flight
    stage(0, 0);
    stage(1, 1);

    int rd = 0;
    for (int kt = 0; kt < KT; kt++) {
        if (kt + 1 < KT) cp_wait<1>();
        else             cp_wait<0>();
        __syncthreads();

        int wr = rd + 2; if (wr >= STAGES) wr -= STAGES;
        if (kt + 2 < KT) stage(kt + 2, wr);

        const uint32_t sA = sbase + (uint32_t)rd * STAGE_BYTES;
        const uint32_t sB = sA + A_BYTES;

        // Register fragment double buffer across the 4 k16 steps
        uint32_t a[2][2][4];   // [buf][mt][4]
        uint32_t b[2][2][4];   // [buf][pp][4]

        auto ldfrag = [&](int t, int buf) {
            const int kc = t * 2;
            #pragma unroll
            for (int mt = 0; mt < 2; mt++)
                ldsm4(a[buf][mt], sA + (uint32_t)(aR[mt] * 128 + (((kc + aCb) ^ aR7[mt]) << 4)));
            #pragma unroll
            for (int pp = 0; pp < 2; pp++)
                ldsm4(b[buf][pp], sB + (uint32_t)(bR[pp] * 128 + (((kc + bCb) ^ bR7[pp]) << 4)));
        };

        ldfrag(0, 0);
        #pragma unroll
        for (int t = 0; t < 4; t++) {
            const int cur = t & 1;
            if (t + 1 < 4) ldfrag(t + 1, cur ^ 1);
            #pragma unroll
            for (int mt = 0; mt < 2; mt++)
                #pragma unroll
                for (int nt = 0; nt < 4; nt++)
                    mma_f16(c[mt][nt], a[cur][mt], &b[cur][nt >> 1][(nt & 1) * 2]);
        }

        rd = rd + 1; if (rd >= STAGES) rd -= STAGES;
    }

    // Epilogue (C frag: lane -> row = base + lane>>2 (+8), cols = 2*(lane&3))
    #pragma unroll
    for (int mt = 0; mt < 2; mt++) {
        #pragma unroll
        for (int half = 0; half < 2; half++) {
            int r = wRow + mt * 16 + (lane >> 2) + half * 8;
            int e = e0 + r;
            if (e >= E) continue;
            if (MODE == 1) {
                int bg = g_bidx[e];
                const float* ugr = &g_ug[(size_t)bg * H_DIM + n0];
                __half*      hr  = &g_hh[(size_t)e * H_DIM + n0];
                #pragma unroll
                for (int nt = 0; nt < 4; nt++) {
                    int col = wCol + nt * 8 + (lane & 3) * 2;
                    float2 g = *(const float2*)&ugr[col];
                    float ox = fmaxf(c[mt][nt][half * 2 + 0] + g.x, 0.f);
                    float oy = fmaxf(c[mt][nt][half * 2 + 1] + g.y, 0.f);
                    *(__half2*)&hr[col] = __floats2half2_rn(ox, oy);
                }
            } else {
                float* orow = &out[(size_t)e * DO_DIM + n0];
                #pragma unroll
                for (int nt = 0; nt < 4; nt++) {
                    int col = wCol + nt * 8 + (lane & 3) * 2;
                    float2 bb = *(const float2*)&bias2[col + n0];
                    float2 o;
                    o.x = c[mt][nt][half * 2 + 0] + bb.x;
                    o.y = c[mt][nt][half * 2 + 1] + bb.y;
                    *(float2*)&orow[col] = o;
                }
            }
        }
    }
}

// ---------------------------------------------------------------------------
// Inputs (metadata order): src, dest, edge_attr, u, batch, W1, b1, W2, b2
// ---------------------------------------------------------------------------
extern "C" void kernel_launch(void* const* d_in, const int* in_sizes, int n_in,
                              void* d_out, int out_size) {
    const float* src   = (const float*)d_in[0];
    const float* dest  = (const float*)d_in[1];
    const float* edge  = (const float*)d_in[2];
    const float* u     = (const float*)d_in[3];
    const int*   batch = (const int*)d_in[4];
    const float* W1    = (const float*)d_in[5];
    const float* b1    = (const float*)d_in[6];
    const float* W2    = (const float*)d_in[7];
    const float* b2    = (const float*)d_in[8];
    float* out = (float*)d_out;

    const int E  = in_sizes[4];
    const int EB = (E + BM - 1) / BM;

    static bool attr_set = false;
    if (!attr_set) {
        cudaFuncSetAttribute(mlp_gemm<1>, cudaFuncAttributeMaxDynamicSharedMemorySize, SMEM_BYTES);
        cudaFuncSetAttribute(mlp_gemm<2>, cudaFuncAttributeMaxDynamicSharedMemorySize, SMEM_BYTES);
        attr_set = true;
    }

    bidx_kernel<<<256, 256>>>(batch, E);
    prep_x<<<2048, 256>>>(src, dest, edge, E);
    prep_w<<<256, 256>>>(W1, W2);
    ug_kernel<<<dim3(B_GR, 4), 128>>>(u, W1, b1);

    dim3 g1(H_DIM / BN, EB);     // n-tiles adjacent -> A rows reused in L2
    mlp_gemm<1><<<g1, 256, SMEM_BYTES>>>(nullptr, nullptr, E);

    dim3 g2(DO_DIM / BN, EB);
    mlp_gemm<2><<<g2, 256, SMEM_BYTES>>>(b2, out, E);
}